// round 3
// baseline (speedup 1.0000x reference)
#include <cuda_runtime.h>
#include <math.h>

// Problem constants
#define BB 2
#define TT 2048
#define CC 1024
#define HH 16
#define HDIM 64
#define BT (BB * TT)      // 4096 rows
#define LOG2T 11

// ----------------------------------------------------------------------------
// Device scratch (static; no allocations allowed)
// ----------------------------------------------------------------------------
static __device__ float g_q[BT * CC];
static __device__ float g_k[BT * CC];
static __device__ float g_v[BT * CC];
static __device__ float g_qr[BT * CC];
static __device__ float g_qi[BT * CC];
static __device__ float g_kr[BT * CC];
static __device__ float g_ki[BT * CC];
static __device__ float g_vr[BT * CC];
static __device__ float g_att[BT * CC];
static __device__ float g_y[BT * CC];
static __device__ float g_inE[BT];

// ----------------------------------------------------------------------------
// Reductions
// ----------------------------------------------------------------------------
__device__ __forceinline__ float blockReduceSum256(float v) {
    __shared__ float red[8];
    int lane = threadIdx.x & 31;
    int w = threadIdx.x >> 5;
#pragma unroll
    for (int o = 16; o >= 1; o >>= 1)
        v += __shfl_xor_sync(0xffffffffu, v, o);
    if (lane == 0) red[w] = v;
    __syncthreads();
    if (w == 0) {
        v = (lane < 8) ? red[lane] : 0.f;
#pragma unroll
        for (int o = 4; o >= 1; o >>= 1)
            v += __shfl_xor_sync(0xffffffffu, v, o);
    }
    return v;  // valid in thread 0
}

// ----------------------------------------------------------------------------
// Input energy: ||x[b,t,:]||_2
// ----------------------------------------------------------------------------
__global__ void energy_in_kernel(const float* __restrict__ x) {
    int row = blockIdx.x;
    const float* xr = x + (size_t)row * CC;
    float s = 0.f;
    for (int c = threadIdx.x; c < CC; c += 256) {
        float v = xr[c];
        s += v * v;
    }
    float tot = blockReduceSum256(s);
    if (threadIdx.x == 0) g_inE[row] = sqrtf(tot);
}

// ----------------------------------------------------------------------------
// GEMM: C[4096,1024] = A[4096,1024] @ W[1024,1024] + bias
// 128x128 tile, BK=16, 256 threads, 8x8 register tile, double-buffered smem
// with register prefetch (one barrier per k-iteration).
// ----------------------------------------------------------------------------
__global__ void __launch_bounds__(256, 2)
gemm4096_kernel(const float* __restrict__ A,
                const float* __restrict__ W,
                const float* __restrict__ bias,
                float* __restrict__ Co) {
    __shared__ __align__(16) float As[2][16][132];
    __shared__ __align__(16) float Bs[2][16][132];
    const int tid = threadIdx.x;
    const int ty = tid >> 4, tx = tid & 15;
    const int m0 = blockIdx.y << 7, n0 = blockIdx.x << 7;
    float acc[8][8] = {};

    // load indices (constant per thread)
    const int e0 = tid, e1 = tid + 256;
    const int ra0 = e0 >> 2, ka0 = (e0 & 3) << 2;
    const int ra1 = e1 >> 2, ka1 = (e1 & 3) << 2;
    const int rb0 = e0 >> 5, cb0 = (e0 & 31) << 2;
    const int rb1 = e1 >> 5, cb1 = (e1 & 31) << 2;

    float4 rA0, rA1, rB0, rB1;
    // preload k0 = 0
    rA0 = *(const float4*)&A[(size_t)(m0 + ra0) * CC + ka0];
    rA1 = *(const float4*)&A[(size_t)(m0 + ra1) * CC + ka1];
    rB0 = *(const float4*)&W[(size_t)rb0 * CC + n0 + cb0];
    rB1 = *(const float4*)&W[(size_t)rb1 * CC + n0 + cb1];
    {
        As[0][ka0 + 0][ra0] = rA0.x; As[0][ka0 + 1][ra0] = rA0.y;
        As[0][ka0 + 2][ra0] = rA0.z; As[0][ka0 + 3][ra0] = rA0.w;
        As[0][ka1 + 0][ra1] = rA1.x; As[0][ka1 + 1][ra1] = rA1.y;
        As[0][ka1 + 2][ra1] = rA1.z; As[0][ka1 + 3][ra1] = rA1.w;
        *(float4*)&Bs[0][rb0][cb0] = rB0;
        *(float4*)&Bs[0][rb1][cb1] = rB1;
    }
    __syncthreads();

    for (int k0 = 0; k0 < CC; k0 += 16) {
        const int p = (k0 >> 4) & 1;
        const bool more = (k0 + 16) < CC;
        if (more) {
            rA0 = *(const float4*)&A[(size_t)(m0 + ra0) * CC + k0 + 16 + ka0];
            rA1 = *(const float4*)&A[(size_t)(m0 + ra1) * CC + k0 + 16 + ka1];
            rB0 = *(const float4*)&W[(size_t)(k0 + 16 + rb0) * CC + n0 + cb0];
            rB1 = *(const float4*)&W[(size_t)(k0 + 16 + rb1) * CC + n0 + cb1];
        }
#pragma unroll
        for (int kk = 0; kk < 16; kk++) {
            float4 a0 = *(const float4*)&As[p][kk][ty << 2];
            float4 a1 = *(const float4*)&As[p][kk][64 + (ty << 2)];
            float4 b0 = *(const float4*)&Bs[p][kk][tx << 2];
            float4 b1 = *(const float4*)&Bs[p][kk][64 + (tx << 2)];
            float av[8] = {a0.x, a0.y, a0.z, a0.w, a1.x, a1.y, a1.z, a1.w};
            float bv[8] = {b0.x, b0.y, b0.z, b0.w, b1.x, b1.y, b1.z, b1.w};
#pragma unroll
            for (int i = 0; i < 8; i++)
#pragma unroll
                for (int j = 0; j < 8; j++)
                    acc[i][j] += av[i] * bv[j];
        }
        if (more) {
            const int q = p ^ 1;
            As[q][ka0 + 0][ra0] = rA0.x; As[q][ka0 + 1][ra0] = rA0.y;
            As[q][ka0 + 2][ra0] = rA0.z; As[q][ka0 + 3][ra0] = rA0.w;
            As[q][ka1 + 0][ra1] = rA1.x; As[q][ka1 + 1][ra1] = rA1.y;
            As[q][ka1 + 2][ra1] = rA1.z; As[q][ka1 + 3][ra1] = rA1.w;
            *(float4*)&Bs[q][rb0][cb0] = rB0;
            *(float4*)&Bs[q][rb1][cb1] = rB1;
        }
        __syncthreads();
    }

#pragma unroll
    for (int i = 0; i < 8; i++) {
        int row = m0 + ((i < 4) ? (ty << 2) + i : 64 + (ty << 2) + i - 4);
#pragma unroll
        for (int jh = 0; jh < 2; jh++) {
            int col = n0 + jh * 64 + (tx << 2);
            float4 o;
            o.x = acc[i][jh * 4 + 0] + bias[col + 0];
            o.y = acc[i][jh * 4 + 1] + bias[col + 1];
            o.z = acc[i][jh * 4 + 2] + bias[col + 2];
            o.w = acc[i][jh * 4 + 3] + bias[col + 3];
            *(float4*)&Co[(size_t)row * CC + col] = o;
        }
    }
}

// ----------------------------------------------------------------------------
// FFT (2048-pt complex, radix-2 DIT) + spectral filter, one block per (b,h,d).
// ----------------------------------------------------------------------------
__global__ void fft_filter_kernel(const float* __restrict__ in,
                                  float* __restrict__ outRe,
                                  float* __restrict__ outIm,
                                  const float* __restrict__ fd,
                                  const float* __restrict__ alpha,
                                  const float* __restrict__ fas) {
    __shared__ float2 sh[TT];
    const int d = blockIdx.x, h = blockIdx.y, b = blockIdx.z;
    const float* src = in + (size_t)b * TT * CC + h * HDIM + d;
    const int tid = threadIdx.x;

#pragma unroll
    for (int i = 0; i < 8; i++) {
        int t = tid + i * 256;
        unsigned r = __brev((unsigned)t) >> (32 - LOG2T);
        sh[r] = make_float2(src[(size_t)t * CC], 0.f);
    }
    __syncthreads();

    for (int st = 1; st <= LOG2T; st++) {
        const int half = 1 << (st - 1);
        const float wstep = -6.283185307179586f / (float)(half * 2);
#pragma unroll
        for (int i = 0; i < 4; i++) {
            int idx = tid + i * 256;
            int pos = idx & (half - 1);
            int grp = idx >> (st - 1);
            int i0 = (grp << st) + pos;
            int i1 = i0 + half;
            float sn, cs;
            __sincosf(wstep * (float)pos, &sn, &cs);
            float2 u = sh[i0], v = sh[i1];
            float tr = cs * v.x - sn * v.y;
            float ti = cs * v.y + sn * v.x;
            sh[i0] = make_float2(u.x + tr, u.y + ti);
            sh[i1] = make_float2(u.x - tr, u.y - ti);
        }
        __syncthreads();
    }

    const float aal = alpha[0] + fas[0] * (fd[0] - 1.5f);
    const size_t obase = ((size_t)(b * HH + h)) * TT * HDIM + d;
#pragma unroll
    for (int i = 0; i < 8; i++) {
        int t = tid + i * 256;
        float fr = (float)(t < TT / 2 ? t : t - TT) * (1.0f / (float)TT);
        float phase = aal * atanf(logf(fabsf(fr) + 1e-10f));
        float sp, cp;
        sincosf(phase, &sp, &cp);
        float2 X = sh[t];
        size_t o = obase + (size_t)t * HDIM;
        outRe[o] = X.x * cp - X.y * sp;
        if (outIm) outIm[o] = X.x * sp + X.y * cp;
    }
}

// ----------------------------------------------------------------------------
// Flash attention per (b,h): S = (Qr Kr^T - Qi Ki^T)/8, online softmax, O=P@Vr.
// t-tile=128, s-tile=64, 256 threads, 8x4 S frags. Next K/V tile prefetched
// into registers under the S-phase FMAs. Separate P smem (no aliasing).
// ----------------------------------------------------------------------------
__global__ void __launch_bounds__(256, 1)
attn_kernel(const float* __restrict__ Qr, const float* __restrict__ Qi,
            const float* __restrict__ Kr, const float* __restrict__ Ki,
            const float* __restrict__ Vr, float* __restrict__ Ao) {
    extern __shared__ __align__(16) float smbuf[];
    float* sQr = smbuf;                 // [d=64][132] (t cols 0..127)
    float* sQi = sQr + 64 * 132;
    float* sKr = sQi + 64 * 132;        // [d=64][68]  (s cols 0..63)
    float* sKi = sKr + 64 * 68;
    float* sV  = sKi + 64 * 68;         // [s=64][68]
    float* sP  = sV + 64 * 68;          // [t=128][68]

    const int tid = threadIdx.x;
    const int ty = tid >> 4, tx = tid & 15;
    const int t0 = blockIdx.x << 7;
    const int h = blockIdx.y, b = blockIdx.z;
    const size_t base = ((size_t)(b * HH + h)) * TT * HDIM;

    int rowIdx[8];
#pragma unroll
    for (int i = 0; i < 8; i++)
        rowIdx[i] = (i < 4) ? (ty << 2) + i : 64 + (ty << 2) + (i - 4);

    // load Q tile (transposed into [d][t])
#pragma unroll
    for (int i = 0; i < 8; i++) {
        int e = tid + i * 256;          // 0..2047
        int r = e >> 4, c4 = (e & 15) << 2;
        size_t g = base + (size_t)(t0 + r) * HDIM + c4;
        float4 qr = *(const float4*)&Qr[g];
        float4 qi = *(const float4*)&Qi[g];
        sQr[(c4 + 0) * 132 + r] = qr.x;
        sQr[(c4 + 1) * 132 + r] = qr.y;
        sQr[(c4 + 2) * 132 + r] = qr.z;
        sQr[(c4 + 3) * 132 + r] = qr.w;
        sQi[(c4 + 0) * 132 + r] = qi.x;
        sQi[(c4 + 1) * 132 + r] = qi.y;
        sQi[(c4 + 2) * 132 + r] = qi.z;
        sQi[(c4 + 3) * 132 + r] = qi.w;
    }

    // K/V prefetch registers: 4 float4 per array
    const int pr = tid >> 4;            // 0..15 base row step 16 -> 4 iters
    const int pc4 = (tid & 15) << 2;
    float4 pKr[4], pKi[4], pV[4];
#pragma unroll
    for (int i = 0; i < 4; i++) {
        size_t g = base + (size_t)(pr + i * 16) * HDIM + pc4;   // s0 = 0
        pKr[i] = *(const float4*)&Kr[g];
        pKi[i] = *(const float4*)&Ki[g];
        pV[i]  = *(const float4*)&Vr[g];
    }

    float m[8], l[8], acc[8][4];
#pragma unroll
    for (int i = 0; i < 8; i++) {
        m[i] = -INFINITY;
        l[i] = 0.f;
#pragma unroll
        for (int j = 0; j < 4; j++) acc[i][j] = 0.f;
    }

    for (int s0 = 0; s0 < TT; s0 += 64) {
        // store prefetched K/V tile to smem
#pragma unroll
        for (int i = 0; i < 4; i++) {
            int r = pr + i * 16;
            sKr[(pc4 + 0) * 68 + r] = pKr[i].x;
            sKr[(pc4 + 1) * 68 + r] = pKr[i].y;
            sKr[(pc4 + 2) * 68 + r] = pKr[i].z;
            sKr[(pc4 + 3) * 68 + r] = pKr[i].w;
            sKi[(pc4 + 0) * 68 + r] = pKi[i].x;
            sKi[(pc4 + 1) * 68 + r] = pKi[i].y;
            sKi[(pc4 + 2) * 68 + r] = pKi[i].z;
            sKi[(pc4 + 3) * 68 + r] = pKi[i].w;
            *(float4*)&sV[r * 68 + pc4] = pV[i];
        }
        __syncthreads();

        // prefetch next tile (hidden under S-phase FMAs)
        if (s0 + 64 < TT) {
#pragma unroll
            for (int i = 0; i < 4; i++) {
                size_t g = base + (size_t)(s0 + 64 + pr + i * 16) * HDIM + pc4;
                pKr[i] = *(const float4*)&Kr[g];
                pKi[i] = *(const float4*)&Ki[g];
                pV[i]  = *(const float4*)&Vr[g];
            }
        }

        // ---- S tile: 8x4 per thread, outer product over d ----
        float S[8][4] = {};
#pragma unroll 4
        for (int d = 0; d < 64; d++) {
            const float* qrp = &sQr[d * 132 + (ty << 2)];
            const float* qip = &sQi[d * 132 + (ty << 2)];
            float4 a0 = *(const float4*)qrp;
            float4 a1 = *(const float4*)(qrp + 64);
            float4 c0 = *(const float4*)qip;
            float4 c1 = *(const float4*)(qip + 64);
            float4 b0 = *(const float4*)&sKr[d * 68 + (tx << 2)];
            float4 e0 = *(const float4*)&sKi[d * 68 + (tx << 2)];
            float qa[8] = {a0.x, a0.y, a0.z, a0.w, a1.x, a1.y, a1.z, a1.w};
            float qb[8] = {c0.x, c0.y, c0.z, c0.w, c1.x, c1.y, c1.z, c1.w};
            float ka[4] = {b0.x, b0.y, b0.z, b0.w};
            float kb[4] = {e0.x, e0.y, e0.z, e0.w};
#pragma unroll
            for (int i = 0; i < 8; i++)
#pragma unroll
                for (int j = 0; j < 4; j++)
                    S[i][j] += qa[i] * ka[j] - qb[i] * kb[j];
        }

        // ---- online softmax; write P ----
#pragma unroll
        for (int i = 0; i < 8; i++) {
            float mx = fmaxf(fmaxf(S[i][0], S[i][1]), fmaxf(S[i][2], S[i][3]));
            mx *= 0.125f;
#pragma unroll
            for (int o = 8; o >= 1; o >>= 1)
                mx = fmaxf(mx, __shfl_xor_sync(0xffffffffu, mx, o));
            float mn = fmaxf(m[i], mx);
            float corr = __expf(m[i] - mn);
            float ps = 0.f;
            float pv[4];
#pragma unroll
            for (int j = 0; j < 4; j++) {
                float p = __expf(S[i][j] * 0.125f - mn);
                pv[j] = p;
                ps += p;
            }
            *(float4*)&sP[rowIdx[i] * 68 + (tx << 2)] =
                make_float4(pv[0], pv[1], pv[2], pv[3]);
#pragma unroll
            for (int o = 8; o >= 1; o >>= 1)
                ps += __shfl_xor_sync(0xffffffffu, ps, o);
            l[i] = l[i] * corr + ps;
            m[i] = mn;
#pragma unroll
            for (int j = 0; j < 4; j++) acc[i][j] *= corr;
        }
        __syncthreads();

        // ---- O += P @ V (2 s-steps per iter, float2 P loads) ----
#pragma unroll 4
        for (int s = 0; s < 64; s += 2) {
            float4 v0 = *(const float4*)&sV[s * 68 + (tx << 2)];
            float4 v1 = *(const float4*)&sV[(s + 1) * 68 + (tx << 2)];
#pragma unroll
            for (int i = 0; i < 8; i++) {
                float2 pp = *(const float2*)&sP[rowIdx[i] * 68 + s];
                acc[i][0] += pp.x * v0.x + pp.y * v1.x;
                acc[i][1] += pp.x * v0.y + pp.y * v1.y;
                acc[i][2] += pp.x * v0.z + pp.y * v1.z;
                acc[i][3] += pp.x * v0.w + pp.y * v1.w;
            }
        }
        __syncthreads();   // protect K/V/P before next tile's stores
    }

    // epilogue: normalize and write [b, t, h*64+d]
#pragma unroll
    for (int i = 0; i < 8; i++) {
        float inv = 1.f / l[i];
        float4 o;
        o.x = acc[i][0] * inv;
        o.y = acc[i][1] * inv;
        o.z = acc[i][2] * inv;
        o.w = acc[i][3] * inv;
        size_t off = ((size_t)(b * TT + t0 + rowIdx[i])) * CC + h * HDIM + (tx << 2);
        *(float4*)&Ao[off] = o;
    }
}

// ----------------------------------------------------------------------------
// Final energy ratio: out = Y * (inE / (||Y row|| + 1e-8)) * energy_normalizer
// ----------------------------------------------------------------------------
__global__ void finalize_kernel(const float* __restrict__ Y,
                                const float* __restrict__ enorm,
                                float* __restrict__ out) {
    int row = blockIdx.x;
    const float* yr = Y + (size_t)row * CC;
    float s = 0.f;
    for (int c = threadIdx.x; c < CC; c += 256) {
        float v = yr[c];
        s += v * v;
    }
    float tot = blockReduceSum256(s);
    __shared__ float ratio;
    if (threadIdx.x == 0)
        ratio = g_inE[row] / (sqrtf(tot) + 1e-8f) * enorm[0];
    __syncthreads();
    for (int c = threadIdx.x; c < CC; c += 256)
        out[(size_t)row * CC + c] = yr[c] * ratio;
}

// ----------------------------------------------------------------------------
// Launch
// ----------------------------------------------------------------------------
extern "C" void kernel_launch(void* const* d_in, const int* in_sizes, int n_in,
                              void* d_out, int out_size) {
    const float* x      = (const float*)d_in[0];
    const float* fd     = (const float*)d_in[1];
    const float* wq     = (const float*)d_in[2];
    const float* bq     = (const float*)d_in[3];
    const float* wk     = (const float*)d_in[4];
    const float* bk     = (const float*)d_in[5];
    const float* wv     = (const float*)d_in[6];
    const float* bv     = (const float*)d_in[7];
    const float* wo     = (const float*)d_in[8];
    const float* bo     = (const float*)d_in[9];
    const float* alpha  = (const float*)d_in[10];
    const float* fas    = (const float*)d_in[11];
    const float* enorm  = (const float*)d_in[12];
    float* out = (float*)d_out;

    float *q, *k, *v, *qr, *qi, *kr, *ki, *vr, *att, *y;
    cudaGetSymbolAddress((void**)&q,  g_q);
    cudaGetSymbolAddress((void**)&k,  g_k);
    cudaGetSymbolAddress((void**)&v,  g_v);
    cudaGetSymbolAddress((void**)&qr, g_qr);
    cudaGetSymbolAddress((void**)&qi, g_qi);
    cudaGetSymbolAddress((void**)&kr, g_kr);
    cudaGetSymbolAddress((void**)&ki, g_ki);
    cudaGetSymbolAddress((void**)&vr, g_vr);
    cudaGetSymbolAddress((void**)&att, g_att);
    cudaGetSymbolAddress((void**)&y,  g_y);

    // input energies
    energy_in_kernel<<<BT, 256>>>(x);

    // QKV projections
    dim3 gg(CC / 128, BT / 128);
    gemm4096_kernel<<<gg, 256>>>(x, wq, bq, q);
    gemm4096_kernel<<<gg, 256>>>(x, wk, bk, k);
    gemm4096_kernel<<<gg, 256>>>(x, wv, bv, v);

    // FFT + spectral filter (V needs only the real part downstream)
    dim3 gf(HDIM, HH, BB);
    fft_filter_kernel<<<gf, 256>>>(q, qr, qi, fd, alpha, fas);
    fft_filter_kernel<<<gf, 256>>>(k, kr, ki, fd, alpha, fas);
    fft_filter_kernel<<<gf, 256>>>(v, vr, nullptr, fd, alpha, fas);

    // attention: smem = (2*64*132 + 3*64*68 + 128*68) * 4 = 154,624 B
    static const int kAttnSmem =
        (2 * 64 * 132 + 3 * 64 * 68 + 128 * 68) * (int)sizeof(float);
    cudaFuncSetAttribute(attn_kernel, cudaFuncAttributeMaxDynamicSharedMemorySize,
                         kAttnSmem);
    dim3 ga(TT / 128, HH, BB);
    attn_kernel<<<ga, 256, kAttnSmem>>>(qr, qi, kr, ki, vr, att);

    // output projection
    gemm4096_kernel<<<gg, 256>>>(att, wo, bo, y);

    // energy-ratio epilogue
    finalize_kernel<<<BT, 256>>>(y, enorm, out);
}

// round 4
// speedup vs baseline: 1.1772x; 1.1772x over previous
#include <cuda_runtime.h>
#include <math.h>

// Problem constants
#define BB 2
#define TT 2048
#define CC 1024
#define HH 16
#define HDIM 64
#define BT (BB * TT)      // 4096 rows
#define LOG2T 11

typedef unsigned long long u64;

// ---------------------------------------------------------------------------
// Packed f32x2 helpers (Blackwell sm_103a): one FMA2 = two fp32 FMAs per issue
// ---------------------------------------------------------------------------
__device__ __forceinline__ u64 pk2(float lo, float hi) {
    u64 r;
    asm("mov.b64 %0, {%1, %2};" : "=l"(r) : "f"(lo), "f"(hi));
    return r;
}
__device__ __forceinline__ u64 dup2(float v) { return pk2(v, v); }
__device__ __forceinline__ void upk2(float& lo, float& hi, u64 v) {
    asm("mov.b64 {%0, %1}, %2;" : "=f"(lo), "=f"(hi) : "l"(v));
}
__device__ __forceinline__ void fma2(u64& d, u64 a, u64 b) {
    asm("fma.rn.f32x2 %0, %1, %2, %0;" : "+l"(d) : "l"(a), "l"(b));
}
__device__ __forceinline__ void mul2(u64& d, u64 a, u64 b) {
    asm("mul.rn.f32x2 %0, %1, %2;" : "=l"(d) : "l"(a), "l"(b));
}

// ----------------------------------------------------------------------------
// Device scratch (static; no allocations allowed)
// ----------------------------------------------------------------------------
static __device__ float g_q[BT * CC];
static __device__ float g_k[BT * CC];
static __device__ float g_v[BT * CC];
static __device__ float g_qr[BT * CC];
static __device__ float g_qi[BT * CC];
static __device__ float g_kr[BT * CC];
static __device__ float g_ki[BT * CC];
static __device__ float g_vr[BT * CC];
static __device__ float g_att[BT * CC];
static __device__ float g_y[BT * CC];
static __device__ float g_inE[BT];

// ----------------------------------------------------------------------------
// Reductions
// ----------------------------------------------------------------------------
__device__ __forceinline__ float blockReduceSum256(float v) {
    __shared__ float red[8];
    int lane = threadIdx.x & 31;
    int w = threadIdx.x >> 5;
#pragma unroll
    for (int o = 16; o >= 1; o >>= 1)
        v += __shfl_xor_sync(0xffffffffu, v, o);
    if (lane == 0) red[w] = v;
    __syncthreads();
    if (w == 0) {
        v = (lane < 8) ? red[lane] : 0.f;
#pragma unroll
        for (int o = 4; o >= 1; o >>= 1)
            v += __shfl_xor_sync(0xffffffffu, v, o);
    }
    return v;  // valid in thread 0
}

// ----------------------------------------------------------------------------
// Input energy: ||x[b,t,:]||_2
// ----------------------------------------------------------------------------
__global__ void energy_in_kernel(const float* __restrict__ x) {
    int row = blockIdx.x;
    const float* xr = x + (size_t)row * CC;
    float s = 0.f;
    for (int c = threadIdx.x; c < CC; c += 256) {
        float v = xr[c];
        s += v * v;
    }
    float tot = blockReduceSum256(s);
    if (threadIdx.x == 0) g_inE[row] = sqrtf(tot);
}

// ----------------------------------------------------------------------------
// GEMM: C[4096,1024] = A[4096,1024] @ W[1024,1024] + bias
// 128x128 tile, BK=16, 256 threads, 8x8 register tile packed as f32x2 pairs
// over the row dimension. Double-buffered smem with register prefetch.
// ----------------------------------------------------------------------------
__global__ void __launch_bounds__(256, 2)
gemm4096_kernel(const float* __restrict__ A,
                const float* __restrict__ W,
                const float* __restrict__ bias,
                float* __restrict__ Co) {
    __shared__ __align__(16) float As[2][16][132];
    __shared__ __align__(16) float Bs[2][16][132];
    const int tid = threadIdx.x;
    const int ty = tid >> 4, tx = tid & 15;
    const int m0 = blockIdx.y << 7, n0 = blockIdx.x << 7;

    // acc2[ip][j]: packed pair of C rows; ip -> rows (see epilogue), j = 8 cols
    u64 acc2[4][8];
#pragma unroll
    for (int i = 0; i < 4; i++)
#pragma unroll
        for (int j = 0; j < 8; j++) acc2[i][j] = 0ull;

    const int e0 = tid, e1 = tid + 256;
    const int ra0 = e0 >> 2, ka0 = (e0 & 3) << 2;
    const int ra1 = e1 >> 2, ka1 = (e1 & 3) << 2;
    const int rb0 = e0 >> 5, cb0 = (e0 & 31) << 2;
    const int rb1 = e1 >> 5, cb1 = (e1 & 31) << 2;

    float4 rA0, rA1, rB0, rB1;
    rA0 = *(const float4*)&A[(size_t)(m0 + ra0) * CC + ka0];
    rA1 = *(const float4*)&A[(size_t)(m0 + ra1) * CC + ka1];
    rB0 = *(const float4*)&W[(size_t)rb0 * CC + n0 + cb0];
    rB1 = *(const float4*)&W[(size_t)rb1 * CC + n0 + cb1];
    {
        As[0][ka0 + 0][ra0] = rA0.x; As[0][ka0 + 1][ra0] = rA0.y;
        As[0][ka0 + 2][ra0] = rA0.z; As[0][ka0 + 3][ra0] = rA0.w;
        As[0][ka1 + 0][ra1] = rA1.x; As[0][ka1 + 1][ra1] = rA1.y;
        As[0][ka1 + 2][ra1] = rA1.z; As[0][ka1 + 3][ra1] = rA1.w;
        *(float4*)&Bs[0][rb0][cb0] = rB0;
        *(float4*)&Bs[0][rb1][cb1] = rB1;
    }
    __syncthreads();

    for (int k0 = 0; k0 < CC; k0 += 16) {
        const int p = (k0 >> 4) & 1;
        const bool more = (k0 + 16) < CC;
        if (more) {
            rA0 = *(const float4*)&A[(size_t)(m0 + ra0) * CC + k0 + 16 + ka0];
            rA1 = *(const float4*)&A[(size_t)(m0 + ra1) * CC + k0 + 16 + ka1];
            rB0 = *(const float4*)&W[(size_t)(k0 + 16 + rb0) * CC + n0 + cb0];
            rB1 = *(const float4*)&W[(size_t)(k0 + 16 + rb1) * CC + n0 + cb1];
        }
#pragma unroll
        for (int kk = 0; kk < 16; kk++) {
            // A rows as packed pairs (direct reinterpret of float4 loads)
            ulonglong2 A0 = *(const ulonglong2*)&As[p][kk][ty << 2];
            ulonglong2 A1 = *(const ulonglong2*)&As[p][kk][64 + (ty << 2)];
            float4 b0 = *(const float4*)&Bs[p][kk][tx << 2];
            float4 b1 = *(const float4*)&Bs[p][kk][64 + (tx << 2)];
            u64 ap[4] = {A0.x, A0.y, A1.x, A1.y};
            u64 bd[8] = {dup2(b0.x), dup2(b0.y), dup2(b0.z), dup2(b0.w),
                         dup2(b1.x), dup2(b1.y), dup2(b1.z), dup2(b1.w)};
#pragma unroll
            for (int i = 0; i < 4; i++)
#pragma unroll
                for (int j = 0; j < 8; j++)
                    fma2(acc2[i][j], ap[i], bd[j]);
        }
        if (more) {
            const int q = p ^ 1;
            As[q][ka0 + 0][ra0] = rA0.x; As[q][ka0 + 1][ra0] = rA0.y;
            As[q][ka0 + 2][ra0] = rA0.z; As[q][ka0 + 3][ra0] = rA0.w;
            As[q][ka1 + 0][ra1] = rA1.x; As[q][ka1 + 1][ra1] = rA1.y;
            As[q][ka1 + 2][ra1] = rA1.z; As[q][ka1 + 3][ra1] = rA1.w;
            *(float4*)&Bs[q][rb0][cb0] = rB0;
            *(float4*)&Bs[q][rb1][cb1] = rB1;
        }
        __syncthreads();
    }

    // epilogue: pair ip covers rows base, base+1
#pragma unroll
    for (int ip = 0; ip < 4; ip++) {
        int base = m0 + ((ip < 2) ? (ty << 2) + 2 * ip
                                  : 64 + (ty << 2) + 2 * (ip - 2));
        float lo[8], hi[8];
#pragma unroll
        for (int j = 0; j < 8; j++) upk2(lo[j], hi[j], acc2[ip][j]);
#pragma unroll
        for (int jh = 0; jh < 2; jh++) {
            int col = n0 + jh * 64 + (tx << 2);
            float4 o0, o1;
            o0.x = lo[jh * 4 + 0] + bias[col + 0];
            o0.y = lo[jh * 4 + 1] + bias[col + 1];
            o0.z = lo[jh * 4 + 2] + bias[col + 2];
            o0.w = lo[jh * 4 + 3] + bias[col + 3];
            o1.x = hi[jh * 4 + 0] + bias[col + 0];
            o1.y = hi[jh * 4 + 1] + bias[col + 1];
            o1.z = hi[jh * 4 + 2] + bias[col + 2];
            o1.w = hi[jh * 4 + 3] + bias[col + 3];
            *(float4*)&Co[(size_t)base * CC + col] = o0;
            *(float4*)&Co[(size_t)(base + 1) * CC + col] = o1;
        }
    }
}

// ----------------------------------------------------------------------------
// FFT (2048-pt complex, radix-2 DIT) + spectral filter, one block per (b,h,d).
// ----------------------------------------------------------------------------
__global__ void fft_filter_kernel(const float* __restrict__ in,
                                  float* __restrict__ outRe,
                                  float* __restrict__ outIm,
                                  const float* __restrict__ fd,
                                  const float* __restrict__ alpha,
                                  const float* __restrict__ fas) {
    __shared__ float2 sh[TT];
    const int d = blockIdx.x, h = blockIdx.y, b = blockIdx.z;
    const float* src = in + (size_t)b * TT * CC + h * HDIM + d;
    const int tid = threadIdx.x;

#pragma unroll
    for (int i = 0; i < 8; i++) {
        int t = tid + i * 256;
        unsigned r = __brev((unsigned)t) >> (32 - LOG2T);
        sh[r] = make_float2(src[(size_t)t * CC], 0.f);
    }
    __syncthreads();

    for (int st = 1; st <= LOG2T; st++) {
        const int half = 1 << (st - 1);
        const float wstep = -6.283185307179586f / (float)(half * 2);
#pragma unroll
        for (int i = 0; i < 4; i++) {
            int idx = tid + i * 256;
            int pos = idx & (half - 1);
            int grp = idx >> (st - 1);
            int i0 = (grp << st) + pos;
            int i1 = i0 + half;
            float sn, cs;
            __sincosf(wstep * (float)pos, &sn, &cs);
            float2 u = sh[i0], v = sh[i1];
            float tr = cs * v.x - sn * v.y;
            float ti = cs * v.y + sn * v.x;
            sh[i0] = make_float2(u.x + tr, u.y + ti);
            sh[i1] = make_float2(u.x - tr, u.y - ti);
        }
        __syncthreads();
    }

    const float aal = alpha[0] + fas[0] * (fd[0] - 1.5f);
    const size_t obase = ((size_t)(b * HH + h)) * TT * HDIM + d;
#pragma unroll
    for (int i = 0; i < 8; i++) {
        int t = tid + i * 256;
        float fr = (float)(t < TT / 2 ? t : t - TT) * (1.0f / (float)TT);
        float phase = aal * atanf(logf(fabsf(fr) + 1e-10f));
        float sp, cp;
        sincosf(phase, &sp, &cp);
        float2 X = sh[t];
        size_t o = obase + (size_t)t * HDIM;
        outRe[o] = X.x * cp - X.y * sp;
        if (outIm) outIm[o] = X.x * sp + X.y * cp;
    }
}

// ----------------------------------------------------------------------------
// Flash attention per (b,h): S = (Qr Kr^T - Qi Ki^T)/8, online softmax, O=P@Vr.
// 128x128 tiles (round-2 structure), 256 threads, f32x2 packed microkernels.
// Ki is stored NEGATED in smem so S accumulates with plain packed FMAs.
// P tile (128x132) aliases the Kr+Ki smem region.
// ----------------------------------------------------------------------------
__global__ void __launch_bounds__(256, 1)
attn_kernel(const float* __restrict__ Qr, const float* __restrict__ Qi,
            const float* __restrict__ Kr, const float* __restrict__ Ki,
            const float* __restrict__ Vr, float* __restrict__ Ao) {
    extern __shared__ __align__(16) float smbuf[];
    float* sQr = smbuf;                 // [d=64][132]
    float* sQi = sQr + 64 * 132;
    float* sKr = sQi + 64 * 132;        // [d=64][132]
    float* sKi = sKr + 64 * 132;        // holds -Ki
    float* sV  = sKi + 64 * 132;        // [s=128][68]
    float* sP  = sKr;                   // [t=128][132], aliases Kr+Ki

    const int tid = threadIdx.x;
    const int ty = tid >> 4, tx = tid & 15;
    const int t0 = blockIdx.x << 7;
    const int h = blockIdx.y, b = blockIdx.z;
    const size_t base = ((size_t)(b * HH + h)) * TT * HDIM;

    int rowIdx[8];
#pragma unroll
    for (int i = 0; i < 8; i++)
        rowIdx[i] = (i < 4) ? (ty << 2) + i : 64 + (ty << 2) + (i - 4);

    // load Q tile (transposed into [d][t])
#pragma unroll
    for (int i = 0; i < 8; i++) {
        int e = tid + i * 256;          // 0..2047
        int r = e >> 4, c4 = (e & 15) << 2;
        size_t g = base + (size_t)(t0 + r) * HDIM + c4;
        float4 qr = *(const float4*)&Qr[g];
        float4 qi = *(const float4*)&Qi[g];
        sQr[(c4 + 0) * 132 + r] = qr.x;
        sQr[(c4 + 1) * 132 + r] = qr.y;
        sQr[(c4 + 2) * 132 + r] = qr.z;
        sQr[(c4 + 3) * 132 + r] = qr.w;
        sQi[(c4 + 0) * 132 + r] = qi.x;
        sQi[(c4 + 1) * 132 + r] = qi.y;
        sQi[(c4 + 2) * 132 + r] = qi.z;
        sQi[(c4 + 3) * 132 + r] = qi.w;
    }

    float m[8], l[8];
    u64 acc2[4][4];                     // packed row pairs (2ip, 2ip+1) x 4 cols
#pragma unroll
    for (int i = 0; i < 8; i++) { m[i] = -INFINITY; l[i] = 0.f; }
#pragma unroll
    for (int i = 0; i < 4; i++)
#pragma unroll
        for (int j = 0; j < 4; j++) acc2[i][j] = 0ull;

    for (int s0 = 0; s0 < TT; s0 += 128) {
        __syncthreads();  // P/V consumed (and Q visible on first iter)
#pragma unroll
        for (int i = 0; i < 8; i++) {
            int e = tid + i * 256;
            int r = e >> 4, c4 = (e & 15) << 2;
            size_t g = base + (size_t)(s0 + r) * HDIM + c4;
            float4 kr = *(const float4*)&Kr[g];
            float4 ki = *(const float4*)&Ki[g];
            sKr[(c4 + 0) * 132 + r] = kr.x;
            sKr[(c4 + 1) * 132 + r] = kr.y;
            sKr[(c4 + 2) * 132 + r] = kr.z;
            sKr[(c4 + 3) * 132 + r] = kr.w;
            sKi[(c4 + 0) * 132 + r] = -ki.x;   // negated: S += qi * (-ki)
            sKi[(c4 + 1) * 132 + r] = -ki.y;
            sKi[(c4 + 2) * 132 + r] = -ki.z;
            sKi[(c4 + 3) * 132 + r] = -ki.w;
            *(float4*)&sV[r * 68 + c4] = *(const float4*)&Vr[g];
        }
        __syncthreads();

        // ---- S tile: packed 4x8 pairs (covers 8x8), outer product over d ----
        u64 S2[4][8];
#pragma unroll
        for (int i = 0; i < 4; i++)
#pragma unroll
            for (int j = 0; j < 8; j++) S2[i][j] = 0ull;

#pragma unroll 4
        for (int d = 0; d < 64; d++) {
            const float* qrp = &sQr[d * 132 + (ty << 2)];
            const float* qip = &sQi[d * 132 + (ty << 2)];
            ulonglong2 QA0 = *(const ulonglong2*)qrp;
            ulonglong2 QA1 = *(const ulonglong2*)(qrp + 64);
            ulonglong2 QB0 = *(const ulonglong2*)qip;
            ulonglong2 QB1 = *(const ulonglong2*)(qip + 64);
            float4 k0 = *(const float4*)&sKr[d * 132 + (tx << 2)];
            float4 k1 = *(const float4*)&sKr[d * 132 + 64 + (tx << 2)];
            float4 j0 = *(const float4*)&sKi[d * 132 + (tx << 2)];
            float4 j1 = *(const float4*)&sKi[d * 132 + 64 + (tx << 2)];
            u64 qa[4] = {QA0.x, QA0.y, QA1.x, QA1.y};
            u64 qb[4] = {QB0.x, QB0.y, QB1.x, QB1.y};
            u64 kd[8] = {dup2(k0.x), dup2(k0.y), dup2(k0.z), dup2(k0.w),
                         dup2(k1.x), dup2(k1.y), dup2(k1.z), dup2(k1.w)};
            u64 jd[8] = {dup2(j0.x), dup2(j0.y), dup2(j0.z), dup2(j0.w),
                         dup2(j1.x), dup2(j1.y), dup2(j1.z), dup2(j1.w)};
#pragma unroll
            for (int i = 0; i < 4; i++)
#pragma unroll
                for (int j = 0; j < 8; j++) {
                    fma2(S2[i][j], qa[i], kd[j]);
                    fma2(S2[i][j], qb[i], jd[j]);
                }
        }
        __syncthreads();  // all K reads done before P overwrites that smem

        // unpack S2 -> S[8][8] (rows rowIdx[2ip], rowIdx[2ip+1])
        float S[8][8];
#pragma unroll
        for (int ip = 0; ip < 4; ip++)
#pragma unroll
            for (int j = 0; j < 8; j++)
                upk2(S[2 * ip][j], S[2 * ip + 1][j], S2[ip][j]);

        // ---- online softmax; write P into aliased smem ----
        float corr[8];
#pragma unroll
        for (int i = 0; i < 8; i++) {
            float mx = S[i][0];
#pragma unroll
            for (int j = 1; j < 8; j++) mx = fmaxf(mx, S[i][j]);
            mx *= 0.125f;
#pragma unroll
            for (int o = 8; o >= 1; o >>= 1)
                mx = fmaxf(mx, __shfl_xor_sync(0xffffffffu, mx, o));
            float mn = fmaxf(m[i], mx);
            corr[i] = __expf(m[i] - mn);
            float ps = 0.f;
            float pv[8];
#pragma unroll
            for (int j = 0; j < 8; j++) {
                float p = __expf(S[i][j] * 0.125f - mn);
                pv[j] = p;
                ps += p;
            }
            *(float4*)&sP[rowIdx[i] * 132 + (tx << 2)] =
                make_float4(pv[0], pv[1], pv[2], pv[3]);
            *(float4*)&sP[rowIdx[i] * 132 + 64 + (tx << 2)] =
                make_float4(pv[4], pv[5], pv[6], pv[7]);
#pragma unroll
            for (int o = 8; o >= 1; o >>= 1)
                ps += __shfl_xor_sync(0xffffffffu, ps, o);
            l[i] = l[i] * corr[i] + ps;
            m[i] = mn;
        }
#pragma unroll
        for (int ip = 0; ip < 4; ip++) {
            u64 c2 = pk2(corr[2 * ip], corr[2 * ip + 1]);
#pragma unroll
            for (int j = 0; j < 4; j++) {
                u64 t;
                mul2(t, acc2[ip][j], c2);
                acc2[ip][j] = t;
            }
        }
        __syncthreads();

        // ---- O += P @ V (packed, 2 s-steps per iter) ----
#pragma unroll 4
        for (int s = 0; s < 128; s += 2) {
            float4 v0 = *(const float4*)&sV[s * 68 + (tx << 2)];
            float4 v1 = *(const float4*)&sV[(s + 1) * 68 + (tx << 2)];
            u64 vd0[4] = {dup2(v0.x), dup2(v0.y), dup2(v0.z), dup2(v0.w)};
            u64 vd1[4] = {dup2(v1.x), dup2(v1.y), dup2(v1.z), dup2(v1.w)};
#pragma unroll
            for (int ip = 0; ip < 4; ip++) {
                float2 pa = *(const float2*)&sP[rowIdx[2 * ip] * 132 + s];
                float2 pb = *(const float2*)&sP[rowIdx[2 * ip + 1] * 132 + s];
                u64 pA = pk2(pa.x, pb.x);
                u64 pB = pk2(pa.y, pb.y);
#pragma unroll
                for (int j = 0; j < 4; j++) {
                    fma2(acc2[ip][j], pA, vd0[j]);
                    fma2(acc2[ip][j], pB, vd1[j]);
                }
            }
        }
    }

    // epilogue: normalize and write [b, t, h*64+d]
#pragma unroll
    for (int ip = 0; ip < 4; ip++) {
        float lo[4], hi[4];
#pragma unroll
        for (int j = 0; j < 4; j++) upk2(lo[j], hi[j], acc2[ip][j]);
        float inv0 = 1.f / l[2 * ip];
        float inv1 = 1.f / l[2 * ip + 1];
        float4 o0 = make_float4(lo[0] * inv0, lo[1] * inv0, lo[2] * inv0, lo[3] * inv0);
        float4 o1 = make_float4(hi[0] * inv1, hi[1] * inv1, hi[2] * inv1, hi[3] * inv1);
        size_t off0 = ((size_t)(b * TT + t0 + rowIdx[2 * ip])) * CC + h * HDIM + (tx << 2);
        size_t off1 = ((size_t)(b * TT + t0 + rowIdx[2 * ip + 1])) * CC + h * HDIM + (tx << 2);
        *(float4*)&Ao[off0] = o0;
        *(float4*)&Ao[off1] = o1;
    }
}

// ----------------------------------------------------------------------------
// Final energy ratio: out = Y * (inE / (||Y row|| + 1e-8)) * energy_normalizer
// ----------------------------------------------------------------------------
__global__ void finalize_kernel(const float* __restrict__ Y,
                                const float* __restrict__ enorm,
                                float* __restrict__ out) {
    int row = blockIdx.x;
    const float* yr = Y + (size_t)row * CC;
    float s = 0.f;
    for (int c = threadIdx.x; c < CC; c += 256) {
        float v = yr[c];
        s += v * v;
    }
    float tot = blockReduceSum256(s);
    __shared__ float ratio;
    if (threadIdx.x == 0)
        ratio = g_inE[row] / (sqrtf(tot) + 1e-8f) * enorm[0];
    __syncthreads();
    for (int c = threadIdx.x; c < CC; c += 256)
        out[(size_t)row * CC + c] = yr[c] * ratio;
}

// ----------------------------------------------------------------------------
// Launch
// ----------------------------------------------------------------------------
extern "C" void kernel_launch(void* const* d_in, const int* in_sizes, int n_in,
                              void* d_out, int out_size) {
    const float* x      = (const float*)d_in[0];
    const float* fd     = (const float*)d_in[1];
    const float* wq     = (const float*)d_in[2];
    const float* bq     = (const float*)d_in[3];
    const float* wk     = (const float*)d_in[4];
    const float* bk     = (const float*)d_in[5];
    const float* wv     = (const float*)d_in[6];
    const float* bv     = (const float*)d_in[7];
    const float* wo     = (const float*)d_in[8];
    const float* bo     = (const float*)d_in[9];
    const float* alpha  = (const float*)d_in[10];
    const float* fas    = (const float*)d_in[11];
    const float* enorm  = (const float*)d_in[12];
    float* out = (float*)d_out;

    float *q, *k, *v, *qr, *qi, *kr, *ki, *vr, *att, *y;
    cudaGetSymbolAddress((void**)&q,  g_q);
    cudaGetSymbolAddress((void**)&k,  g_k);
    cudaGetSymbolAddress((void**)&v,  g_v);
    cudaGetSymbolAddress((void**)&qr, g_qr);
    cudaGetSymbolAddress((void**)&qi, g_qi);
    cudaGetSymbolAddress((void**)&kr, g_kr);
    cudaGetSymbolAddress((void**)&ki, g_ki);
    cudaGetSymbolAddress((void**)&vr, g_vr);
    cudaGetSymbolAddress((void**)&att, g_att);
    cudaGetSymbolAddress((void**)&y,  g_y);

    // input energies
    energy_in_kernel<<<BT, 256>>>(x);

    // QKV projections
    dim3 gg(CC / 128, BT / 128);
    gemm4096_kernel<<<gg, 256>>>(x, wq, bq, q);
    gemm4096_kernel<<<gg, 256>>>(x, wk, bk, k);
    gemm4096_kernel<<<gg, 256>>>(x, wv, bv, v);

    // FFT + spectral filter (V needs only the real part downstream)
    dim3 gf(HDIM, HH, BB);
    fft_filter_kernel<<<gf, 256>>>(q, qr, qi, fd, alpha, fas);
    fft_filter_kernel<<<gf, 256>>>(k, kr, ki, fd, alpha, fas);
    fft_filter_kernel<<<gf, 256>>>(v, vr, nullptr, fd, alpha, fas);

    // attention: smem = (4*64*132 + 128*68) floats = 169,984 B
    static const int kAttnSmem = (4 * 64 * 132 + 128 * 68) * (int)sizeof(float);
    cudaFuncSetAttribute(attn_kernel, cudaFuncAttributeMaxDynamicSharedMemorySize,
                         kAttnSmem);
    dim3 ga(TT / 128, HH, BB);
    attn_kernel<<<ga, 256, kAttnSmem>>>(qr, qi, kr, ki, vr, att);

    // output projection
    gemm4096_kernel<<<gg, 256>>>(att, wo, bo, y);

    // energy-ratio epilogue
    finalize_kernel<<<BT, 256>>>(y, enorm, out);
}

// round 5
// speedup vs baseline: 1.1935x; 1.0139x over previous
#include <cuda_runtime.h>
#include <math.h>

// Problem constants
#define BB 2
#define TT 2048
#define CC 1024
#define HH 16
#define HDIM 64
#define BT (BB * TT)      // 4096 rows
#define LOG2T 11

typedef unsigned long long u64;

// ---------------------------------------------------------------------------
// Packed f32x2 helpers (Blackwell sm_103a)
// ---------------------------------------------------------------------------
__device__ __forceinline__ u64 pk2(float lo, float hi) {
    u64 r;
    asm("mov.b64 %0, {%1, %2};" : "=l"(r) : "f"(lo), "f"(hi));
    return r;
}
__device__ __forceinline__ u64 dup2(float v) { return pk2(v, v); }
__device__ __forceinline__ void upk2(float& lo, float& hi, u64 v) {
    asm("mov.b64 {%0, %1}, %2;" : "=f"(lo), "=f"(hi) : "l"(v));
}
__device__ __forceinline__ void fma2(u64& d, u64 a, u64 b) {
    asm("fma.rn.f32x2 %0, %1, %2, %0;" : "+l"(d) : "l"(a), "l"(b));
}
__device__ __forceinline__ void mul2(u64& d, u64 a, u64 b) {
    asm("mul.rn.f32x2 %0, %1, %2;" : "=l"(d) : "l"(a), "l"(b));
}

// ----------------------------------------------------------------------------
// Device scratch (static; no allocations allowed)
// ----------------------------------------------------------------------------
static __device__ float g_q[BT * CC];
static __device__ float g_k[BT * CC];
static __device__ float g_v[BT * CC];
static __device__ float g_qr[BT * CC];
static __device__ float g_qi[BT * CC];
static __device__ float g_kr[BT * CC];
static __device__ float g_ki[BT * CC];
static __device__ float g_vr[BT * CC];
static __device__ float g_att[BT * CC];
static __device__ float g_y[BT * CC];
static __device__ float g_inE[BT];

// ----------------------------------------------------------------------------
// Reductions
// ----------------------------------------------------------------------------
__device__ __forceinline__ float blockReduceSum256(float v) {
    __shared__ float red[8];
    int lane = threadIdx.x & 31;
    int w = threadIdx.x >> 5;
#pragma unroll
    for (int o = 16; o >= 1; o >>= 1)
        v += __shfl_xor_sync(0xffffffffu, v, o);
    if (lane == 0) red[w] = v;
    __syncthreads();
    if (w == 0) {
        v = (lane < 8) ? red[lane] : 0.f;
#pragma unroll
        for (int o = 4; o >= 1; o >>= 1)
            v += __shfl_xor_sync(0xffffffffu, v, o);
    }
    return v;  // valid in thread 0
}

// ----------------------------------------------------------------------------
// Input energy: ||x[b,t,:]||_2
// ----------------------------------------------------------------------------
__global__ void energy_in_kernel(const float* __restrict__ x) {
    int row = blockIdx.x;
    const float* xr = x + (size_t)row * CC;
    float s = 0.f;
    for (int c = threadIdx.x; c < CC; c += 256) {
        float v = xr[c];
        s += v * v;
    }
    float tot = blockReduceSum256(s);
    if (threadIdx.x == 0) g_inE[row] = sqrtf(tot);
}

// ----------------------------------------------------------------------------
// GEMM: C[4096,1024] = A[4096,1024] @ W[1024,1024] + bias
// 128x128 tile, BK=16, 256 threads, 8x8 tile packed f32x2, double-buffered.
// ----------------------------------------------------------------------------
__global__ void __launch_bounds__(256, 2)
gemm4096_kernel(const float* __restrict__ A,
                const float* __restrict__ W,
                const float* __restrict__ bias,
                float* __restrict__ Co) {
    __shared__ __align__(16) float As[2][16][132];
    __shared__ __align__(16) float Bs[2][16][132];
    const int tid = threadIdx.x;
    const int ty = tid >> 4, tx = tid & 15;
    const int m0 = blockIdx.y << 7, n0 = blockIdx.x << 7;

    u64 acc2[4][8];
#pragma unroll
    for (int i = 0; i < 4; i++)
#pragma unroll
        for (int j = 0; j < 8; j++) acc2[i][j] = 0ull;

    const int e0 = tid, e1 = tid + 256;
    const int ra0 = e0 >> 2, ka0 = (e0 & 3) << 2;
    const int ra1 = e1 >> 2, ka1 = (e1 & 3) << 2;
    const int rb0 = e0 >> 5, cb0 = (e0 & 31) << 2;
    const int rb1 = e1 >> 5, cb1 = (e1 & 31) << 2;

    float4 rA0, rA1, rB0, rB1;
    rA0 = *(const float4*)&A[(size_t)(m0 + ra0) * CC + ka0];
    rA1 = *(const float4*)&A[(size_t)(m0 + ra1) * CC + ka1];
    rB0 = *(const float4*)&W[(size_t)rb0 * CC + n0 + cb0];
    rB1 = *(const float4*)&W[(size_t)rb1 * CC + n0 + cb1];
    {
        As[0][ka0 + 0][ra0] = rA0.x; As[0][ka0 + 1][ra0] = rA0.y;
        As[0][ka0 + 2][ra0] = rA0.z; As[0][ka0 + 3][ra0] = rA0.w;
        As[0][ka1 + 0][ra1] = rA1.x; As[0][ka1 + 1][ra1] = rA1.y;
        As[0][ka1 + 2][ra1] = rA1.z; As[0][ka1 + 3][ra1] = rA1.w;
        *(float4*)&Bs[0][rb0][cb0] = rB0;
        *(float4*)&Bs[0][rb1][cb1] = rB1;
    }
    __syncthreads();

    for (int k0 = 0; k0 < CC; k0 += 16) {
        const int p = (k0 >> 4) & 1;
        const bool more = (k0 + 16) < CC;
        if (more) {
            rA0 = *(const float4*)&A[(size_t)(m0 + ra0) * CC + k0 + 16 + ka0];
            rA1 = *(const float4*)&A[(size_t)(m0 + ra1) * CC + k0 + 16 + ka1];
            rB0 = *(const float4*)&W[(size_t)(k0 + 16 + rb0) * CC + n0 + cb0];
            rB1 = *(const float4*)&W[(size_t)(k0 + 16 + rb1) * CC + n0 + cb1];
        }
#pragma unroll
        for (int kk = 0; kk < 16; kk++) {
            ulonglong2 A0 = *(const ulonglong2*)&As[p][kk][ty << 2];
            ulonglong2 A1 = *(const ulonglong2*)&As[p][kk][64 + (ty << 2)];
            float4 b0 = *(const float4*)&Bs[p][kk][tx << 2];
            float4 b1 = *(const float4*)&Bs[p][kk][64 + (tx << 2)];
            u64 ap[4] = {A0.x, A0.y, A1.x, A1.y};
            u64 bd[8] = {dup2(b0.x), dup2(b0.y), dup2(b0.z), dup2(b0.w),
                         dup2(b1.x), dup2(b1.y), dup2(b1.z), dup2(b1.w)};
#pragma unroll
            for (int i = 0; i < 4; i++)
#pragma unroll
                for (int j = 0; j < 8; j++)
                    fma2(acc2[i][j], ap[i], bd[j]);
        }
        if (more) {
            const int q = p ^ 1;
            As[q][ka0 + 0][ra0] = rA0.x; As[q][ka0 + 1][ra0] = rA0.y;
            As[q][ka0 + 2][ra0] = rA0.z; As[q][ka0 + 3][ra0] = rA0.w;
            As[q][ka1 + 0][ra1] = rA1.x; As[q][ka1 + 1][ra1] = rA1.y;
            As[q][ka1 + 2][ra1] = rA1.z; As[q][ka1 + 3][ra1] = rA1.w;
            *(float4*)&Bs[q][rb0][cb0] = rB0;
            *(float4*)&Bs[q][rb1][cb1] = rB1;
        }
        __syncthreads();
    }

#pragma unroll
    for (int ip = 0; ip < 4; ip++) {
        int base = m0 + ((ip < 2) ? (ty << 2) + 2 * ip
                                  : 64 + (ty << 2) + 2 * (ip - 2));
        float lo[8], hi[8];
#pragma unroll
        for (int j = 0; j < 8; j++) upk2(lo[j], hi[j], acc2[ip][j]);
#pragma unroll
        for (int jh = 0; jh < 2; jh++) {
            int col = n0 + jh * 64 + (tx << 2);
            float4 o0, o1;
            o0.x = lo[jh * 4 + 0] + bias[col + 0];
            o0.y = lo[jh * 4 + 1] + bias[col + 1];
            o0.z = lo[jh * 4 + 2] + bias[col + 2];
            o0.w = lo[jh * 4 + 3] + bias[col + 3];
            o1.x = hi[jh * 4 + 0] + bias[col + 0];
            o1.y = hi[jh * 4 + 1] + bias[col + 1];
            o1.z = hi[jh * 4 + 2] + bias[col + 2];
            o1.w = hi[jh * 4 + 3] + bias[col + 3];
            *(float4*)&Co[(size_t)base * CC + col] = o0;
            *(float4*)&Co[(size_t)(base + 1) * CC + col] = o1;
        }
    }
}

// ----------------------------------------------------------------------------
// Batched FFT: one block per (b, h, group of 8 head-dims).
// Loads are 32B-sector dense; twiddles shared across the 8 columns; outputs
// stored as 2x float4 per (t, group). smem: [2048][9] float2 (147456 B).
// ----------------------------------------------------------------------------
#define FSTR 9
__global__ void __launch_bounds__(256, 1)
fft_filter_kernel(const float* __restrict__ in,
                  float* __restrict__ outRe,
                  float* __restrict__ outIm,
                  const float* __restrict__ fd,
                  const float* __restrict__ alpha,
                  const float* __restrict__ fas) {
    extern __shared__ __align__(16) float2 sh[];   // sh[t*FSTR + c], c<8
    const int dg = blockIdx.x;     // d-group 0..7 (8 dims each)
    const int h = blockIdx.y, b = blockIdx.z;
    const int col0 = h * HDIM + dg * 8;
    const float* src = in + (size_t)b * TT * CC + col0;
    const int tid = threadIdx.x;

    // load 2048 x 8 floats (4 float2 per t), bit-reversed rows
#pragma unroll
    for (int i = 0; i < 32; i++) {
        int e = tid + i * 256;
        int t = e >> 2, pr = e & 3;
        float2 v = *(const float2*)&src[(size_t)t * CC + pr * 2];
        unsigned r = __brev((unsigned)t) >> (32 - LOG2T);
        sh[r * FSTR + pr * 2]     = make_float2(v.x, 0.f);
        sh[r * FSTR + pr * 2 + 1] = make_float2(v.y, 0.f);
    }
    __syncthreads();

    // forward FFT (numpy convention), twiddle shared across 8 columns
    for (int st = 1; st <= LOG2T; st++) {
        const int half = 1 << (st - 1);
        const float wstep = -6.283185307179586f / (float)(half * 2);
#pragma unroll
        for (int w = 0; w < 4; w++) {
            int idx = tid + w * 256;               // butterfly 0..1023
            int pos = idx & (half - 1);
            int grp = idx >> (st - 1);
            int i0 = (grp << st) + pos;
            int i1 = i0 + half;
            float sn, cs;
            __sincosf(wstep * (float)pos, &sn, &cs);
            float2* p0 = &sh[i0 * FSTR];
            float2* p1 = &sh[i1 * FSTR];
#pragma unroll
            for (int c = 0; c < 8; c++) {
                float2 u = p0[c], v = p1[c];
                float tr = cs * v.x - sn * v.y;
                float ti = cs * v.y + sn * v.x;
                p0[c] = make_float2(u.x + tr, u.y + ti);
                p1[c] = make_float2(u.x - tr, u.y - ti);
            }
        }
        __syncthreads();
    }

    // spectral filter + store (phase shared across the 8 columns)
    const float aal = alpha[0] + fas[0] * (fd[0] - 1.5f);
    const size_t obase = ((size_t)(b * HH + h)) * TT * HDIM + dg * 8;
#pragma unroll
    for (int i = 0; i < 8; i++) {
        int t = tid + i * 256;
        float fr = (float)(t < TT / 2 ? t : t - TT) * (1.0f / (float)TT);
        float phase = aal * atanf(logf(fabsf(fr) + 1e-10f));
        float sp, cp;
        sincosf(phase, &sp, &cp);
        const float2* p = &sh[t * FSTR];
        float re[8], im[8];
#pragma unroll
        for (int c = 0; c < 8; c++) {
            float2 X = p[c];
            re[c] = X.x * cp - X.y * sp;
            im[c] = X.x * sp + X.y * cp;
        }
        size_t o = obase + (size_t)t * HDIM;
        *(float4*)&outRe[o]     = make_float4(re[0], re[1], re[2], re[3]);
        *(float4*)&outRe[o + 4] = make_float4(re[4], re[5], re[6], re[7]);
        if (outIm) {
            *(float4*)&outIm[o]     = make_float4(im[0], im[1], im[2], im[3]);
            *(float4*)&outIm[o + 4] = make_float4(im[4], im[5], im[6], im[7]);
        }
    }
}

// ----------------------------------------------------------------------------
// Flash attention per (b,h): S = (Qr Kr^T - Qi Ki^T)/8, online softmax, O=P@Vr.
// 128x128 tiles, 512 threads (16 warps/SM), 4x8 per-thread tile, f32x2 packed.
// Ki stored NEGATED; P tile aliases Kr+Ki smem.
// ----------------------------------------------------------------------------
__global__ void __launch_bounds__(512, 1)
attn_kernel(const float* __restrict__ Qr, const float* __restrict__ Qi,
            const float* __restrict__ Kr, const float* __restrict__ Ki,
            const float* __restrict__ Vr, float* __restrict__ Ao) {
    extern __shared__ __align__(16) float smbuf[];
    float* sQr = smbuf;                 // [d=64][132]
    float* sQi = sQr + 64 * 132;
    float* sKr = sQi + 64 * 132;        // [d=64][132]
    float* sKi = sKr + 64 * 132;        // holds -Ki
    float* sV  = sKi + 64 * 132;        // [s=128][68]
    float* sP  = sKr;                   // [t=128][132], aliases Kr+Ki

    const int tid = threadIdx.x;
    const int ty = tid >> 4, tx = tid & 15;   // ty 0..31, tx 0..15
    const int t0 = blockIdx.x << 7;
    const int h = blockIdx.y, b = blockIdx.z;
    const size_t base = ((size_t)(b * HH + h)) * TT * HDIM;
    const int r0 = ty << 2;                   // 4 contiguous rows per thread

    // load Q tile (transposed into [d][t])
#pragma unroll
    for (int i = 0; i < 4; i++) {
        int e = tid + i * 512;          // 0..2047
        int r = e >> 4, c4 = (e & 15) << 2;
        size_t g = base + (size_t)(t0 + r) * HDIM + c4;
        float4 qr = *(const float4*)&Qr[g];
        float4 qi = *(const float4*)&Qi[g];
        sQr[(c4 + 0) * 132 + r] = qr.x;
        sQr[(c4 + 1) * 132 + r] = qr.y;
        sQr[(c4 + 2) * 132 + r] = qr.z;
        sQr[(c4 + 3) * 132 + r] = qr.w;
        sQi[(c4 + 0) * 132 + r] = qi.x;
        sQi[(c4 + 1) * 132 + r] = qi.y;
        sQi[(c4 + 2) * 132 + r] = qi.z;
        sQi[(c4 + 3) * 132 + r] = qi.w;
    }

    float m[4], l[4];
    u64 acc2[2][4];                     // packed row pairs (r0+2i, r0+2i+1)
#pragma unroll
    for (int i = 0; i < 4; i++) { m[i] = -INFINITY; l[i] = 0.f; }
#pragma unroll
    for (int i = 0; i < 2; i++)
#pragma unroll
        for (int j = 0; j < 4; j++) acc2[i][j] = 0ull;

    for (int s0 = 0; s0 < TT; s0 += 128) {
        __syncthreads();  // P/V consumed (and Q visible on first iter)
#pragma unroll
        for (int i = 0; i < 4; i++) {
            int e = tid + i * 512;
            int r = e >> 4, c4 = (e & 15) << 2;
            size_t g = base + (size_t)(s0 + r) * HDIM + c4;
            float4 kr = *(const float4*)&Kr[g];
            float4 ki = *(const float4*)&Ki[g];
            sKr[(c4 + 0) * 132 + r] = kr.x;
            sKr[(c4 + 1) * 132 + r] = kr.y;
            sKr[(c4 + 2) * 132 + r] = kr.z;
            sKr[(c4 + 3) * 132 + r] = kr.w;
            sKi[(c4 + 0) * 132 + r] = -ki.x;
            sKi[(c4 + 1) * 132 + r] = -ki.y;
            sKi[(c4 + 2) * 132 + r] = -ki.z;
            sKi[(c4 + 3) * 132 + r] = -ki.w;
            *(float4*)&sV[r * 68 + c4] = *(const float4*)&Vr[g];
        }
        __syncthreads();

        // ---- S tile: packed 2x8 pairs (covers 4x8), outer product over d ----
        u64 S2[2][8];
#pragma unroll
        for (int i = 0; i < 2; i++)
#pragma unroll
            for (int j = 0; j < 8; j++) S2[i][j] = 0ull;

#pragma unroll 4
        for (int d = 0; d < 64; d++) {
            ulonglong2 QA = *(const ulonglong2*)&sQr[d * 132 + r0];
            ulonglong2 QB = *(const ulonglong2*)&sQi[d * 132 + r0];
            float4 k0 = *(const float4*)&sKr[d * 132 + (tx << 2)];
            float4 k1 = *(const float4*)&sKr[d * 132 + 64 + (tx << 2)];
            float4 j0 = *(const float4*)&sKi[d * 132 + (tx << 2)];
            float4 j1 = *(const float4*)&sKi[d * 132 + 64 + (tx << 2)];
            u64 qa[2] = {QA.x, QA.y};
            u64 qb[2] = {QB.x, QB.y};
            u64 kd[8] = {dup2(k0.x), dup2(k0.y), dup2(k0.z), dup2(k0.w),
                         dup2(k1.x), dup2(k1.y), dup2(k1.z), dup2(k1.w)};
            u64 jd[8] = {dup2(j0.x), dup2(j0.y), dup2(j0.z), dup2(j0.w),
                         dup2(j1.x), dup2(j1.y), dup2(j1.z), dup2(j1.w)};
#pragma unroll
            for (int i = 0; i < 2; i++)
#pragma unroll
                for (int j = 0; j < 8; j++) {
                    fma2(S2[i][j], qa[i], kd[j]);
                    fma2(S2[i][j], qb[i], jd[j]);
                }
        }
        __syncthreads();  // all K reads done before P overwrites that smem

        float S[4][8];
#pragma unroll
        for (int ip = 0; ip < 2; ip++)
#pragma unroll
            for (int j = 0; j < 8; j++)
                upk2(S[2 * ip][j], S[2 * ip + 1][j], S2[ip][j]);

        // ---- online softmax; write P into aliased smem ----
        float corr[4];
#pragma unroll
        for (int i = 0; i < 4; i++) {
            float mx = S[i][0];
#pragma unroll
            for (int j = 1; j < 8; j++) mx = fmaxf(mx, S[i][j]);
            mx *= 0.125f;
#pragma unroll
            for (int o = 8; o >= 1; o >>= 1)
                mx = fmaxf(mx, __shfl_xor_sync(0xffffffffu, mx, o));
            float mn = fmaxf(m[i], mx);
            corr[i] = __expf(m[i] - mn);
            float ps = 0.f;
            float pv[8];
#pragma unroll
            for (int j = 0; j < 8; j++) {
                float p = __expf(S[i][j] * 0.125f - mn);
                pv[j] = p;
                ps += p;
            }
            *(float4*)&sP[(r0 + i) * 132 + (tx << 2)] =
                make_float4(pv[0], pv[1], pv[2], pv[3]);
            *(float4*)&sP[(r0 + i) * 132 + 64 + (tx << 2)] =
                make_float4(pv[4], pv[5], pv[6], pv[7]);
#pragma unroll
            for (int o = 8; o >= 1; o >>= 1)
                ps += __shfl_xor_sync(0xffffffffu, ps, o);
            l[i] = l[i] * corr[i] + ps;
            m[i] = mn;
        }
#pragma unroll
        for (int ip = 0; ip < 2; ip++) {
            u64 c2 = pk2(corr[2 * ip], corr[2 * ip + 1]);
#pragma unroll
            for (int j = 0; j < 4; j++) {
                u64 t;
                mul2(t, acc2[ip][j], c2);
                acc2[ip][j] = t;
            }
        }
        __syncthreads();

        // ---- O += P @ V (packed, 2 s-steps per iter) ----
#pragma unroll 4
        for (int s = 0; s < 128; s += 2) {
            float4 v0 = *(const float4*)&sV[s * 68 + (tx << 2)];
            float4 v1 = *(const float4*)&sV[(s + 1) * 68 + (tx << 2)];
            u64 vd0[4] = {dup2(v0.x), dup2(v0.y), dup2(v0.z), dup2(v0.w)};
            u64 vd1[4] = {dup2(v1.x), dup2(v1.y), dup2(v1.z), dup2(v1.w)};
#pragma unroll
            for (int ip = 0; ip < 2; ip++) {
                float2 pa = *(const float2*)&sP[(r0 + 2 * ip) * 132 + s];
                float2 pb = *(const float2*)&sP[(r0 + 2 * ip + 1) * 132 + s];
                u64 pA = pk2(pa.x, pb.x);
                u64 pB = pk2(pa.y, pb.y);
#pragma unroll
                for (int j = 0; j < 4; j++) {
                    fma2(acc2[ip][j], pA, vd0[j]);
                    fma2(acc2[ip][j], pB, vd1[j]);
                }
            }
        }
    }

    // epilogue: normalize and write [b, t, h*64+d]
#pragma unroll
    for (int ip = 0; ip < 2; ip++) {
        float lo[4], hi[4];
#pragma unroll
        for (int j = 0; j < 4; j++) upk2(lo[j], hi[j], acc2[ip][j]);
        float inv0 = 1.f / l[2 * ip];
        float inv1 = 1.f / l[2 * ip + 1];
        float4 o0 = make_float4(lo[0] * inv0, lo[1] * inv0, lo[2] * inv0, lo[3] * inv0);
        float4 o1 = make_float4(hi[0] * inv1, hi[1] * inv1, hi[2] * inv1, hi[3] * inv1);
        size_t off0 = ((size_t)(b * TT + t0 + r0 + 2 * ip)) * CC + h * HDIM + (tx << 2);
        size_t off1 = ((size_t)(b * TT + t0 + r0 + 2 * ip + 1)) * CC + h * HDIM + (tx << 2);
        *(float4*)&Ao[off0] = o0;
        *(float4*)&Ao[off1] = o1;
    }
}

// ----------------------------------------------------------------------------
// Final energy ratio: out = Y * (inE / (||Y row|| + 1e-8)) * energy_normalizer
// ----------------------------------------------------------------------------
__global__ void finalize_kernel(const float* __restrict__ Y,
                                const float* __restrict__ enorm,
                                float* __restrict__ out) {
    int row = blockIdx.x;
    const float* yr = Y + (size_t)row * CC;
    float s = 0.f;
    for (int c = threadIdx.x; c < CC; c += 256) {
        float v = yr[c];
        s += v * v;
    }
    float tot = blockReduceSum256(s);
    __shared__ float ratio;
    if (threadIdx.x == 0)
        ratio = g_inE[row] / (sqrtf(tot) + 1e-8f) * enorm[0];
    __syncthreads();
    for (int c = threadIdx.x; c < CC; c += 256)
        out[(size_t)row * CC + c] = yr[c] * ratio;
}

// ----------------------------------------------------------------------------
// Launch
// ----------------------------------------------------------------------------
extern "C" void kernel_launch(void* const* d_in, const int* in_sizes, int n_in,
                              void* d_out, int out_size) {
    const float* x      = (const float*)d_in[0];
    const float* fd     = (const float*)d_in[1];
    const float* wq     = (const float*)d_in[2];
    const float* bq     = (const float*)d_in[3];
    const float* wk     = (const float*)d_in[4];
    const float* bk     = (const float*)d_in[5];
    const float* wv     = (const float*)d_in[6];
    const float* bv     = (const float*)d_in[7];
    const float* wo     = (const float*)d_in[8];
    const float* bo     = (const float*)d_in[9];
    const float* alpha  = (const float*)d_in[10];
    const float* fas    = (const float*)d_in[11];
    const float* enorm  = (const float*)d_in[12];
    float* out = (float*)d_out;

    float *q, *k, *v, *qr, *qi, *kr, *ki, *vr, *att, *y;
    cudaGetSymbolAddress((void**)&q,  g_q);
    cudaGetSymbolAddress((void**)&k,  g_k);
    cudaGetSymbolAddress((void**)&v,  g_v);
    cudaGetSymbolAddress((void**)&qr, g_qr);
    cudaGetSymbolAddress((void**)&qi, g_qi);
    cudaGetSymbolAddress((void**)&kr, g_kr);
    cudaGetSymbolAddress((void**)&ki, g_ki);
    cudaGetSymbolAddress((void**)&vr, g_vr);
    cudaGetSymbolAddress((void**)&att, g_att);
    cudaGetSymbolAddress((void**)&y,  g_y);

    // input energies
    energy_in_kernel<<<BT, 256>>>(x);

    // QKV projections
    dim3 gg(CC / 128, BT / 128);
    gemm4096_kernel<<<gg, 256>>>(x, wq, bq, q);
    gemm4096_kernel<<<gg, 256>>>(x, wk, bk, k);
    gemm4096_kernel<<<gg, 256>>>(x, wv, bv, v);

    // FFT + spectral filter, 8 columns per block; smem = 2048*9*8 = 147456 B
    static const int kFftSmem = TT * FSTR * (int)sizeof(float2);
    cudaFuncSetAttribute(fft_filter_kernel,
                         cudaFuncAttributeMaxDynamicSharedMemorySize, kFftSmem);
    dim3 gf(HDIM / 8, HH, BB);
    fft_filter_kernel<<<gf, 256, kFftSmem>>>(q, qr, qi, fd, alpha, fas);
    fft_filter_kernel<<<gf, 256, kFftSmem>>>(k, kr, ki, fd, alpha, fas);
    fft_filter_kernel<<<gf, 256, kFftSmem>>>(v, vr, nullptr, fd, alpha, fas);

    // attention: smem = (4*64*132 + 128*68) floats = 169,984 B
    static const int kAttnSmem = (4 * 64 * 132 + 128 * 68) * (int)sizeof(float);
    cudaFuncSetAttribute(attn_kernel, cudaFuncAttributeMaxDynamicSharedMemorySize,
                         kAttnSmem);
    dim3 ga(TT / 128, HH, BB);
    attn_kernel<<<ga, 512, kAttnSmem>>>(qr, qi, kr, ki, vr, att);

    // output projection
    gemm4096_kernel<<<gg, 256>>>(att, wo, bo, y);

    // energy-ratio epilogue
    finalize_kernel<<<BT, 256>>>(y, enorm, out);
}

// round 7
// speedup vs baseline: 1.2333x; 1.0333x over previous
#include <cuda_runtime.h>
#include <math.h>
#include <cstdint>

// Problem constants
#define BB 2
#define TT 2048
#define CC 1024
#define HH 16
#define HDIM 64
#define BT (BB * TT)      // 4096 rows
#define LOG2T 11

typedef unsigned long long u64;
typedef unsigned int u32;

// ---------------------------------------------------------------------------
// Packed f32x2 helpers (Blackwell sm_103a)
// ---------------------------------------------------------------------------
__device__ __forceinline__ u64 pk2(float lo, float hi) {
    u64 r;
    asm("mov.b64 %0, {%1, %2};" : "=l"(r) : "f"(lo), "f"(hi));
    return r;
}
__device__ __forceinline__ u64 dup2(float v) { return pk2(v, v); }
__device__ __forceinline__ void upk2(float& lo, float& hi, u64 v) {
    asm("mov.b64 {%0, %1}, %2;" : "=f"(lo), "=f"(hi) : "l"(v));
}
__device__ __forceinline__ void fma2(u64& d, u64 a, u64 b) {
    asm("fma.rn.f32x2 %0, %1, %2, %0;" : "+l"(d) : "l"(a), "l"(b));
}
__device__ __forceinline__ void mul2(u64& d, u64 a, u64 b) {
    asm("mul.rn.f32x2 %0, %1, %2;" : "=l"(d) : "l"(a), "l"(b));
}
__device__ __forceinline__ void cpasync16(u32 smem_dst, const void* gptr) {
    asm volatile("cp.async.ca.shared.global [%0], [%1], 16;"
                 :: "r"(smem_dst), "l"(gptr));
}
__device__ __forceinline__ void cpcommit() {
    asm volatile("cp.async.commit_group;");
}
__device__ __forceinline__ void cpwait0() {
    asm volatile("cp.async.wait_group 0;");
}

// ----------------------------------------------------------------------------
// Device scratch (static; no allocations allowed)
// ----------------------------------------------------------------------------
static __device__ float g_q[BT * CC];
static __device__ float g_k[BT * CC];
static __device__ float g_v[BT * CC];
static __device__ float g_qr[BT * CC];
static __device__ float g_qi[BT * CC];
static __device__ float g_kr[BT * CC];
static __device__ float g_ki[BT * CC];
static __device__ float g_vr[BT * CC];
static __device__ float g_att[BT * CC];
static __device__ float g_y[BT * CC];
static __device__ float g_inE[BT];

// ----------------------------------------------------------------------------
// Reductions
// ----------------------------------------------------------------------------
__device__ __forceinline__ float blockReduceSum256(float v) {
    __shared__ float red[8];
    int lane = threadIdx.x & 31;
    int w = threadIdx.x >> 5;
#pragma unroll
    for (int o = 16; o >= 1; o >>= 1)
        v += __shfl_xor_sync(0xffffffffu, v, o);
    if (lane == 0) red[w] = v;
    __syncthreads();
    if (w == 0) {
        v = (lane < 8) ? red[lane] : 0.f;
#pragma unroll
        for (int o = 4; o >= 1; o >>= 1)
            v += __shfl_xor_sync(0xffffffffu, v, o);
    }
    return v;  // valid in thread 0
}

// ----------------------------------------------------------------------------
// Input energy: ||x[b,t,:]||_2
// ----------------------------------------------------------------------------
__global__ void energy_in_kernel(const float* __restrict__ x) {
    int row = blockIdx.x;
    const float* xr = x + (size_t)row * CC;
    float s = 0.f;
    for (int c = threadIdx.x; c < CC; c += 256) {
        float v = xr[c];
        s += v * v;
    }
    float tot = blockReduceSum256(s);
    if (threadIdx.x == 0) g_inE[row] = sqrtf(tot);
}

// ----------------------------------------------------------------------------
// GEMM: C[4096,1024] = A[4096,1024] @ W[1024,1024] + bias
// 128x128 tile, BK=32, 256 threads, 8x8 f32x2-packed tile. Double-buffered:
// B via cp.async (no regs, no store phase), A via register prefetch
// (transposed smem store). One barrier per 32-k block.
// ----------------------------------------------------------------------------
#define GBK 32
__global__ void __launch_bounds__(256, 2)
gemm4096_kernel(const float* __restrict__ A,
                const float* __restrict__ W,
                const float* __restrict__ bias,
                float* __restrict__ Co) {
    extern __shared__ __align__(16) float dsm[];
    // As[2][GBK][132], Bs[2][GBK][132]
    float* AsBase = dsm;
    float* BsBase = dsm + 2 * GBK * 132;
    const u32 bsU32 = (u32)__cvta_generic_to_shared(BsBase);

    const int tid = threadIdx.x;
    const int ty = tid >> 4, tx = tid & 15;
    const int m0 = blockIdx.y << 7, n0 = blockIdx.x << 7;

    u64 acc2[4][8];
#pragma unroll
    for (int i = 0; i < 4; i++)
#pragma unroll
        for (int j = 0; j < 8; j++) acc2[i][j] = 0ull;

    // per-thread load coords
    int raI[4], kaI[4], rbI[4], cbI[4];
#pragma unroll
    for (int i = 0; i < 4; i++) {
        int e = tid + i * 256;          // 0..1023
        raI[i] = e >> 3;                // A: 128 rows x 8 float4
        kaI[i] = (e & 7) << 2;
        rbI[i] = e >> 5;                // B: 32 rows x 32 float4
        cbI[i] = (e & 31) << 2;
    }

    float4 rA[4];
    // ---- preload k-block 0 ----
#pragma unroll
    for (int i = 0; i < 4; i++) {
        rA[i] = *(const float4*)&A[(size_t)(m0 + raI[i]) * CC + kaI[i]];
        const float* gB = &W[(size_t)rbI[i] * CC + n0 + cbI[i]];
        cpasync16(bsU32 + (u32)((rbI[i] * 132 + cbI[i]) * 4), gB);
    }
    cpcommit();
#pragma unroll
    for (int i = 0; i < 4; i++) {
        float* as = &AsBase[kaI[i] * 132 + raI[i]];
        as[0 * 132] = rA[i].x; as[1 * 132] = rA[i].y;
        as[2 * 132] = rA[i].z; as[3 * 132] = rA[i].w;
    }
    cpwait0();
    __syncthreads();

    for (int k0 = 0; k0 < CC; k0 += GBK) {
        const int p = (k0 / GBK) & 1;
        const int q = p ^ 1;
        const bool more = (k0 + GBK) < CC;
        if (more) {
            // prefetch next B straight to smem, next A to regs
#pragma unroll
            for (int i = 0; i < 4; i++) {
                const float* gB =
                    &W[(size_t)(k0 + GBK + rbI[i]) * CC + n0 + cbI[i]];
                cpasync16(bsU32 + (u32)(((q * GBK + rbI[i]) * 132 +
                                         cbI[i]) * 4), gB);
                rA[i] = *(const float4*)
                    &A[(size_t)(m0 + raI[i]) * CC + k0 + GBK + kaI[i]];
            }
            cpcommit();
        }
        const float* As = &AsBase[p * GBK * 132];
        const float* Bs = &BsBase[p * GBK * 132];
#pragma unroll 16
        for (int kk = 0; kk < GBK; kk++) {
            ulonglong2 A0 = *(const ulonglong2*)&As[kk * 132 + (ty << 2)];
            ulonglong2 A1 = *(const ulonglong2*)&As[kk * 132 + 64 + (ty << 2)];
            float4 b0 = *(const float4*)&Bs[kk * 132 + (tx << 2)];
            float4 b1 = *(const float4*)&Bs[kk * 132 + 64 + (tx << 2)];
            u64 ap[4] = {A0.x, A0.y, A1.x, A1.y};
            u64 bd[8] = {dup2(b0.x), dup2(b0.y), dup2(b0.z), dup2(b0.w),
                         dup2(b1.x), dup2(b1.y), dup2(b1.z), dup2(b1.w)};
#pragma unroll
            for (int i = 0; i < 4; i++)
#pragma unroll
                for (int j = 0; j < 8; j++)
                    fma2(acc2[i][j], ap[i], bd[j]);
        }
        if (more) {
#pragma unroll
            for (int i = 0; i < 4; i++) {
                float* as = &AsBase[(q * GBK + kaI[i]) * 132 + raI[i]];
                as[0 * 132] = rA[i].x; as[1 * 132] = rA[i].y;
                as[2 * 132] = rA[i].z; as[3 * 132] = rA[i].w;
            }
            cpwait0();
        }
        __syncthreads();
    }

#pragma unroll
    for (int ip = 0; ip < 4; ip++) {
        int base = m0 + ((ip < 2) ? (ty << 2) + 2 * ip
                                  : 64 + (ty << 2) + 2 * (ip - 2));
        float lo[8], hi[8];
#pragma unroll
        for (int j = 0; j < 8; j++) upk2(lo[j], hi[j], acc2[ip][j]);
#pragma unroll
        for (int jh = 0; jh < 2; jh++) {
            int col = n0 + jh * 64 + (tx << 2);
            float4 o0, o1;
            o0.x = lo[jh * 4 + 0] + bias[col + 0];
            o0.y = lo[jh * 4 + 1] + bias[col + 1];
            o0.z = lo[jh * 4 + 2] + bias[col + 2];
            o0.w = lo[jh * 4 + 3] + bias[col + 3];
            o1.x = hi[jh * 4 + 0] + bias[col + 0];
            o1.y = hi[jh * 4 + 1] + bias[col + 1];
            o1.z = hi[jh * 4 + 2] + bias[col + 2];
            o1.w = hi[jh * 4 + 3] + bias[col + 3];
            *(float4*)&Co[(size_t)base * CC + col] = o0;
            *(float4*)&Co[(size_t)(base + 1) * CC + col] = o1;
        }
    }
}

// ----------------------------------------------------------------------------
// Batched FFT: one block per (tensor, b, h, 8-dim group). All three tensors
// (Q, K, V) handled by one launch; twiddles shared across the 8 columns.
// ----------------------------------------------------------------------------
#define FSTR 9
__global__ void __launch_bounds__(256, 1)
fft_filter_kernel(const float* __restrict__ inQ, const float* __restrict__ inK,
                  const float* __restrict__ inV,
                  float* __restrict__ oQr, float* __restrict__ oQi,
                  float* __restrict__ oKr, float* __restrict__ oKi,
                  float* __restrict__ oVr,
                  const float* __restrict__ fd,
                  const float* __restrict__ alpha,
                  const float* __restrict__ fas) {
    extern __shared__ __align__(16) float2 sh[];   // sh[t*FSTR + c], c<8
    const int dg = blockIdx.x;          // d-group 0..7
    const int which = blockIdx.y >> 4;  // 0=Q 1=K 2=V
    const int h = blockIdx.y & 15;
    const int b = blockIdx.z;
    const float* in = (which == 0) ? inQ : (which == 1) ? inK : inV;
    float* outRe = (which == 0) ? oQr : (which == 1) ? oKr : oVr;
    float* outIm = (which == 0) ? oQi : (which == 1) ? oKi : (float*)0;

    const int col0 = h * HDIM + dg * 8;
    const float* src = in + (size_t)b * TT * CC + col0;
    const int tid = threadIdx.x;

#pragma unroll
    for (int i = 0; i < 32; i++) {
        int e = tid + i * 256;
        int t = e >> 2, pr = e & 3;
        float2 v = *(const float2*)&src[(size_t)t * CC + pr * 2];
        unsigned r = __brev((unsigned)t) >> (32 - LOG2T);
        sh[r * FSTR + pr * 2]     = make_float2(v.x, 0.f);
        sh[r * FSTR + pr * 2 + 1] = make_float2(v.y, 0.f);
    }
    __syncthreads();

    for (int st = 1; st <= LOG2T; st++) {
        const int half = 1 << (st - 1);
        const float wstep = -6.283185307179586f / (float)(half * 2);
#pragma unroll
        for (int w = 0; w < 4; w++) {
            int idx = tid + w * 256;
            int pos = idx & (half - 1);
            int grp = idx >> (st - 1);
            int i0 = (grp << st) + pos;
            int i1 = i0 + half;
            float sn, cs;
            __sincosf(wstep * (float)pos, &sn, &cs);
            float2* p0 = &sh[i0 * FSTR];
            float2* p1 = &sh[i1 * FSTR];
#pragma unroll
            for (int c = 0; c < 8; c++) {
                float2 u = p0[c], v = p1[c];
                float tr = cs * v.x - sn * v.y;
                float ti = cs * v.y + sn * v.x;
                p0[c] = make_float2(u.x + tr, u.y + ti);
                p1[c] = make_float2(u.x - tr, u.y - ti);
            }
        }
        __syncthreads();
    }

    const float aal = alpha[0] + fas[0] * (fd[0] - 1.5f);
    const size_t obase = ((size_t)(b * HH + h)) * TT * HDIM + dg * 8;
#pragma unroll
    for (int i = 0; i < 8; i++) {
        int t = tid + i * 256;
        float fr = (float)(t < TT / 2 ? t : t - TT) * (1.0f / (float)TT);
        float phase = aal * atanf(logf(fabsf(fr) + 1e-10f));
        float sp, cp;
        sincosf(phase, &sp, &cp);
        const float2* p = &sh[t * FSTR];
        float re[8], im[8];
#pragma unroll
        for (int c = 0; c < 8; c++) {
            float2 X = p[c];
            re[c] = X.x * cp - X.y * sp;
            im[c] = X.x * sp + X.y * cp;
        }
        size_t o = obase + (size_t)t * HDIM;
        *(float4*)&outRe[o]     = make_float4(re[0], re[1], re[2], re[3]);
        *(float4*)&outRe[o + 4] = make_float4(re[4], re[5], re[6], re[7]);
        if (outIm) {
            *(float4*)&outIm[o]     = make_float4(im[0], im[1], im[2], im[3]);
            *(float4*)&outIm[o + 4] = make_float4(im[4], im[5], im[6], im[7]);
        }
    }
}

// ----------------------------------------------------------------------------
// Flash attention per (b,h). 128x128 tiles, 512 threads, column-packed f32x2:
// K/V operand pairs come straight from smem as u64 (no dup2); only Q/P
// broadcasts use dup2. Ki stored NEGATED; P aliases Kr+Ki smem.
// ----------------------------------------------------------------------------
__global__ void __launch_bounds__(512, 1)
attn_kernel(const float* __restrict__ Qr, const float* __restrict__ Qi,
            const float* __restrict__ Kr, const float* __restrict__ Ki,
            const float* __restrict__ Vr, float* __restrict__ Ao) {
    extern __shared__ __align__(16) float smbuf[];
    float* sQr = smbuf;                 // [d=64][132]
    float* sQi = sQr + 64 * 132;
    float* sKr = sQi + 64 * 132;        // [d=64][132]
    float* sKi = sKr + 64 * 132;        // holds -Ki
    float* sV  = sKi + 64 * 132;        // [s=128][68]
    float* sP  = sKr;                   // [t=128][132], aliases Kr+Ki

    const int tid = threadIdx.x;
    const int ty = tid >> 4, tx = tid & 15;   // ty 0..31, tx 0..15
    const int t0 = blockIdx.x << 7;
    const int h = blockIdx.y, b = blockIdx.z;
    const size_t base = ((size_t)(b * HH + h)) * TT * HDIM;
    const int r0 = ty << 2;                   // 4 rows per thread
    const int c0 = tx << 2;                   // 4+4 cols per thread

    // load Q tile (transposed into [d][t])
#pragma unroll
    for (int i = 0; i < 4; i++) {
        int e = tid + i * 512;          // 0..2047
        int r = e >> 4, c4 = (e & 15) << 2;
        size_t g = base + (size_t)(t0 + r) * HDIM + c4;
        float4 qr = *(const float4*)&Qr[g];
        float4 qi = *(const float4*)&Qi[g];
        sQr[(c4 + 0) * 132 + r] = qr.x;
        sQr[(c4 + 1) * 132 + r] = qr.y;
        sQr[(c4 + 2) * 132 + r] = qr.z;
        sQr[(c4 + 3) * 132 + r] = qr.w;
        sQi[(c4 + 0) * 132 + r] = qi.x;
        sQi[(c4 + 1) * 132 + r] = qi.y;
        sQi[(c4 + 2) * 132 + r] = qi.z;
        sQi[(c4 + 3) * 132 + r] = qi.w;
    }

    float m[4], l[4];
    u64 acc2[4][2];                     // [row][col-pair]; pairs (c0+2cp, +1)
#pragma unroll
    for (int i = 0; i < 4; i++) { m[i] = -INFINITY; l[i] = 0.f; }
#pragma unroll
    for (int i = 0; i < 4; i++) { acc2[i][0] = 0ull; acc2[i][1] = 0ull; }

    for (int s0 = 0; s0 < TT; s0 += 128) {
        __syncthreads();  // P/V consumed (and Q visible on first iter)
#pragma unroll
        for (int i = 0; i < 4; i++) {
            int e = tid + i * 512;
            int r = e >> 4, c4 = (e & 15) << 2;
            size_t g = base + (size_t)(s0 + r) * HDIM + c4;
            float4 kr = *(const float4*)&Kr[g];
            float4 ki = *(const float4*)&Ki[g];
            sKr[(c4 + 0) * 132 + r] = kr.x;
            sKr[(c4 + 1) * 132 + r] = kr.y;
            sKr[(c4 + 2) * 132 + r] = kr.z;
            sKr[(c4 + 3) * 132 + r] = kr.w;
            sKi[(c4 + 0) * 132 + r] = -ki.x;
            sKi[(c4 + 1) * 132 + r] = -ki.y;
            sKi[(c4 + 2) * 132 + r] = -ki.z;
            sKi[(c4 + 3) * 132 + r] = -ki.w;
            *(float4*)&sV[r * 68 + c4] = *(const float4*)&Vr[g];
        }
        __syncthreads();

        // ---- S tile: [4 rows][4 col-pairs]; K pairs direct from smem ----
        u64 S2[4][4];
#pragma unroll
        for (int i = 0; i < 4; i++)
#pragma unroll
            for (int j = 0; j < 4; j++) S2[i][j] = 0ull;

#pragma unroll 4
        for (int d = 0; d < 64; d++) {
            float4 q4 = *(const float4*)&sQr[d * 132 + r0];
            float4 p4 = *(const float4*)&sQi[d * 132 + r0];
            ulonglong2 K0 = *(const ulonglong2*)&sKr[d * 132 + c0];
            ulonglong2 K1 = *(const ulonglong2*)&sKr[d * 132 + 64 + c0];
            ulonglong2 J0 = *(const ulonglong2*)&sKi[d * 132 + c0];
            ulonglong2 J1 = *(const ulonglong2*)&sKi[d * 132 + 64 + c0];
            u64 kp[4] = {K0.x, K0.y, K1.x, K1.y};
            u64 jp[4] = {J0.x, J0.y, J1.x, J1.y};
            float qv[4] = {q4.x, q4.y, q4.z, q4.w};
            float pv_[4] = {p4.x, p4.y, p4.z, p4.w};
#pragma unroll
            for (int i = 0; i < 4; i++) {
                u64 qd = dup2(qv[i]);
                u64 pd = dup2(pv_[i]);
#pragma unroll
                for (int cp = 0; cp < 4; cp++) {
                    fma2(S2[i][cp], qd, kp[cp]);
                    fma2(S2[i][cp], pd, jp[cp]);
                }
            }
        }
        __syncthreads();  // all K reads done before P overwrites that smem

        // unpack: cp0,cp1 -> cols c0..c0+3 ; cp2,cp3 -> cols 64+c0..64+c0+3
        float S[4][8];
#pragma unroll
        for (int i = 0; i < 4; i++)
#pragma unroll
            for (int cp = 0; cp < 4; cp++)
                upk2(S[i][2 * cp], S[i][2 * cp + 1], S2[i][cp]);

        // ---- online softmax; write P into aliased smem ----
        float corr[4];
#pragma unroll
        for (int i = 0; i < 4; i++) {
            float mx = S[i][0];
#pragma unroll
            for (int j = 1; j < 8; j++) mx = fmaxf(mx, S[i][j]);
            mx *= 0.125f;
#pragma unroll
            for (int o = 8; o >= 1; o >>= 1)
                mx = fmaxf(mx, __shfl_xor_sync(0xffffffffu, mx, o));
            float mn = fmaxf(m[i], mx);
            corr[i] = __expf(m[i] - mn);
            float ps = 0.f;
            float pv[8];
#pragma unroll
            for (int j = 0; j < 8; j++) {
                float p = __expf(S[i][j] * 0.125f - mn);
                pv[j] = p;
                ps += p;
            }
            *(float4*)&sP[(r0 + i) * 132 + c0] =
                make_float4(pv[0], pv[1], pv[2], pv[3]);
            *(float4*)&sP[(r0 + i) * 132 + 64 + c0] =
                make_float4(pv[4], pv[5], pv[6], pv[7]);
#pragma unroll
            for (int o = 8; o >= 1; o >>= 1)
                ps += __shfl_xor_sync(0xffffffffu, ps, o);
            l[i] = l[i] * corr[i] + ps;
            m[i] = mn;
        }
#pragma unroll
        for (int i = 0; i < 4; i++) {
            u64 cd = dup2(corr[i]);
            u64 t0r, t1r;
            mul2(t0r, acc2[i][0], cd);
            mul2(t1r, acc2[i][1], cd);
            acc2[i][0] = t0r;
            acc2[i][1] = t1r;
        }
        __syncthreads();

        // ---- O += P @ V: V pairs direct from smem, P scalars dup'd ----
#pragma unroll 4
        for (int s = 0; s < 128; s += 2) {
            ulonglong2 V0 = *(const ulonglong2*)&sV[s * 68 + c0];
            ulonglong2 V1 = *(const ulonglong2*)&sV[(s + 1) * 68 + c0];
#pragma unroll
            for (int i = 0; i < 4; i++) {
                float2 pp = *(const float2*)&sP[(r0 + i) * 132 + s];
                u64 pd0 = dup2(pp.x);
                u64 pd1 = dup2(pp.y);
                fma2(acc2[i][0], pd0, V0.x);
                fma2(acc2[i][1], pd0, V0.y);
                fma2(acc2[i][0], pd1, V1.x);
                fma2(acc2[i][1], pd1, V1.y);
            }
        }
    }

    // epilogue: normalize and write [b, t, h*64+d]
#pragma unroll
    for (int i = 0; i < 4; i++) {
        float a0, a1, a2, a3;
        upk2(a0, a1, acc2[i][0]);
        upk2(a2, a3, acc2[i][1]);
        float inv = 1.f / l[i];
        float4 o = make_float4(a0 * inv, a1 * inv, a2 * inv, a3 * inv);
        size_t off = ((size_t)(b * TT + t0 + r0 + i)) * CC + h * HDIM + c0;
        *(float4*)&Ao[off] = o;
    }
}

// ----------------------------------------------------------------------------
// Final energy ratio: out = Y * (inE / (||Y row|| + 1e-8)) * energy_normalizer
// ----------------------------------------------------------------------------
__global__ void finalize_kernel(const float* __restrict__ Y,
                                const float* __restrict__ enorm,
                                float* __restrict__ out) {
    int row = blockIdx.x;
    const float* yr = Y + (size_t)row * CC;
    float s = 0.f;
    for (int c = threadIdx.x; c < CC; c += 256) {
        float v = yr[c];
        s += v * v;
    }
    float tot = blockReduceSum256(s);
    __shared__ float ratio;
    if (threadIdx.x == 0)
        ratio = g_inE[row] / (sqrtf(tot) + 1e-8f) * enorm[0];
    __syncthreads();
    for (int c = threadIdx.x; c < CC; c += 256)
        out[(size_t)row * CC + c] = yr[c] * ratio;
}

// ----------------------------------------------------------------------------
// Launch
// ----------------------------------------------------------------------------
extern "C" void kernel_launch(void* const* d_in, const int* in_sizes, int n_in,
                              void* d_out, int out_size) {
    const float* x      = (const float*)d_in[0];
    const float* fd     = (const float*)d_in[1];
    const float* wq     = (const float*)d_in[2];
    const float* bq     = (const float*)d_in[3];
    const float* wk     = (const float*)d_in[4];
    const float* bk     = (const float*)d_in[5];
    const float* wv     = (const float*)d_in[6];
    const float* bv     = (const float*)d_in[7];
    const float* wo     = (const float*)d_in[8];
    const float* bo     = (const float*)d_in[9];
    const float* alpha  = (const float*)d_in[10];
    const float* fas    = (const float*)d_in[11];
    const float* enorm  = (const float*)d_in[12];
    float* out = (float*)d_out;

    float *q, *k, *v, *qr, *qi, *kr, *ki, *vr, *att, *y;
    cudaGetSymbolAddress((void**)&q,  g_q);
    cudaGetSymbolAddress((void**)&k,  g_k);
    cudaGetSymbolAddress((void**)&v,  g_v);
    cudaGetSymbolAddress((void**)&qr, g_qr);
    cudaGetSymbolAddress((void**)&qi, g_qi);
    cudaGetSymbolAddress((void**)&kr, g_kr);
    cudaGetSymbolAddress((void**)&ki, g_ki);
    cudaGetSymbolAddress((void**)&vr, g_vr);
    cudaGetSymbolAddress((void**)&att, g_att);
    cudaGetSymbolAddress((void**)&y,  g_y);

    // input energies
    energy_in_kernel<<<BT, 256>>>(x);

    // QKV projections: smem = 2 * 2 * 32 * 132 * 4 = 67584 B
    static const int kGemmSmem = 2 * 2 * GBK * 132 * (int)sizeof(float);
    cudaFuncSetAttribute(gemm4096_kernel,
                         cudaFuncAttributeMaxDynamicSharedMemorySize, kGemmSmem);
    dim3 gg(CC / 128, BT / 128);
    gemm4096_kernel<<<gg, 256, kGemmSmem>>>(x, wq, bq, q);
    gemm4096_kernel<<<gg, 256, kGemmSmem>>>(x, wk, bk, k);
    gemm4096_kernel<<<gg, 256, kGemmSmem>>>(x, wv, bv, v);

    // FFT + spectral filter, all three tensors in one launch
    static const int kFftSmem = TT * FSTR * (int)sizeof(float2);  // 147456
    cudaFuncSetAttribute(fft_filter_kernel,
                         cudaFuncAttributeMaxDynamicSharedMemorySize, kFftSmem);
    dim3 gf(HDIM / 8, HH * 3, BB);
    fft_filter_kernel<<<gf, 256, kFftSmem>>>(q, k, v, qr, qi, kr, ki, vr,
                                             fd, alpha, fas);

    // attention: smem = (4*64*132 + 128*68) floats = 169,984 B
    static const int kAttnSmem = (4 * 64 * 132 + 128 * 68) * (int)sizeof(float);
    cudaFuncSetAttribute(attn_kernel, cudaFuncAttributeMaxDynamicSharedMemorySize,
                         kAttnSmem);
    dim3 ga(TT / 128, HH, BB);
    attn_kernel<<<ga, 512, kAttnSmem>>>(qr, qi, kr, ki, vr, att);

    // output projection
    gemm4096_kernel<<<gg, 256, kGemmSmem>>>(att, wo, bo, y);

    // energy-ratio epilogue
    finalize_kernel<<<BT, 256>>>(y, enorm, out);
}

// round 9
// speedup vs baseline: 1.2778x; 1.0360x over previous
#include <cuda_runtime.h>
#include <cuda_bf16.h>
#include <math.h>
#include <cstdint>

// Problem constants
#define BB 2
#define TT 2048
#define CC 1024
#define HH 16
#define HDIM 64
#define BT (BB * TT)      // 4096 rows
#define LOG2T 11

typedef unsigned long long u64;
typedef unsigned int u32;

// ---------------------------------------------------------------------------
// Packed f32x2 helpers (Blackwell sm_103a)
// ---------------------------------------------------------------------------
__device__ __forceinline__ u64 pk2(float lo, float hi) {
    u64 r;
    asm("mov.b64 %0, {%1, %2};" : "=l"(r) : "f"(lo), "f"(hi));
    return r;
}
__device__ __forceinline__ u64 dup2(float v) { return pk2(v, v); }
__device__ __forceinline__ void upk2(float& lo, float& hi, u64 v) {
    asm("mov.b64 {%0, %1}, %2;" : "=f"(lo), "=f"(hi) : "l"(v));
}
__device__ __forceinline__ void fma2(u64& d, u64 a, u64 b) {
    asm("fma.rn.f32x2 %0, %1, %2, %0;" : "+l"(d) : "l"(a), "l"(b));
}
__device__ __forceinline__ void mul2(u64& d, u64 a, u64 b) {
    asm("mul.rn.f32x2 %0, %1, %2;" : "=l"(d) : "l"(a), "l"(b));
}

// ---------------------------------------------------------------------------
// mma.sync / ldmatrix / cp.async helpers (compute_103-legal PTX)
// ---------------------------------------------------------------------------
__device__ __forceinline__ u32 smem_u32(const void* p) {
    u32 a;
    asm("{ .reg .u64 t; cvta.to.shared.u64 t, %1; cvt.u32.u64 %0, t; }"
        : "=r"(a) : "l"(p));
    return a;
}
__device__ __forceinline__ void cpasync16(u32 smem_dst, const void* gptr) {
    asm volatile("cp.async.ca.shared.global [%0], [%1], 16;"
                 :: "r"(smem_dst), "l"(gptr));
}
__device__ __forceinline__ void cpcommit() {
    asm volatile("cp.async.commit_group;");
}
__device__ __forceinline__ void cpwait0() {
    asm volatile("cp.async.wait_group 0;");
}
__device__ __forceinline__ void ldsm_x4(u32& r0, u32& r1, u32& r2, u32& r3,
                                        u32 addr) {
    asm volatile("ldmatrix.sync.aligned.m8n8.x4.shared.b16 {%0,%1,%2,%3}, [%4];"
                 : "=r"(r0), "=r"(r1), "=r"(r2), "=r"(r3) : "r"(addr));
}
__device__ __forceinline__ void mma_bf16(float* c, const u32* a, const u32* b) {
    asm volatile(
        "mma.sync.aligned.m16n8k16.row.col.f32.bf16.bf16.f32 "
        "{%0,%1,%2,%3}, {%4,%5,%6,%7}, {%8,%9}, {%0,%1,%2,%3};"
        : "+f"(c[0]), "+f"(c[1]), "+f"(c[2]), "+f"(c[3])
        : "r"(a[0]), "r"(a[1]), "r"(a[2]), "r"(a[3]), "r"(b[0]), "r"(b[1]));
}

// ----------------------------------------------------------------------------
// Device scratch (static; no allocations allowed)
// ----------------------------------------------------------------------------
static __device__ float g_q[BT * CC];
static __device__ float g_k[BT * CC];
static __device__ float g_v[BT * CC];
static __device__ float g_qr[BT * CC];
static __device__ float g_qi[BT * CC];
static __device__ float g_kr[BT * CC];
static __device__ float g_ki[BT * CC];
static __device__ float g_vr[BT * CC];
static __device__ float g_att[BT * CC];
static __device__ float g_y[BT * CC];
static __device__ float g_inE[BT];
// bf16x3 splits
static __device__ __nv_bfloat16 g_xh[BT * CC];
static __device__ __nv_bfloat16 g_xm[BT * CC];
static __device__ __nv_bfloat16 g_xl[BT * CC];
static __device__ __nv_bfloat16 g_wt[12 * CC * CC];   // 4 weights x {h,m,l}, [N][K]

// ----------------------------------------------------------------------------
// Reductions
// ----------------------------------------------------------------------------
__device__ __forceinline__ float blockReduceSum256(float v) {
    __shared__ float red[8];
    int lane = threadIdx.x & 31;
    int w = threadIdx.x >> 5;
#pragma unroll
    for (int o = 16; o >= 1; o >>= 1)
        v += __shfl_xor_sync(0xffffffffu, v, o);
    if (lane == 0) red[w] = v;
    __syncthreads();
    if (w == 0) {
        v = (lane < 8) ? red[lane] : 0.f;
#pragma unroll
        for (int o = 4; o >= 1; o >>= 1)
            v += __shfl_xor_sync(0xffffffffu, v, o);
    }
    return v;  // valid in thread 0
}

// ----------------------------------------------------------------------------
// Input energy: ||x[b,t,:]||_2
// ----------------------------------------------------------------------------
__global__ void energy_in_kernel(const float* __restrict__ x) {
    int row = blockIdx.x;
    const float* xr = x + (size_t)row * CC;
    float s = 0.f;
    for (int c = threadIdx.x; c < CC; c += 256) {
        float v = xr[c];
        s += v * v;
    }
    float tot = blockReduceSum256(s);
    if (threadIdx.x == 0) g_inE[row] = sqrtf(tot);
}

// ----------------------------------------------------------------------------
// Split fp32 -> 3x bf16 (hi, mid, lo), elementwise (2 elems/thread)
// ----------------------------------------------------------------------------
__global__ void asplit_kernel(const float* __restrict__ X,
                              __nv_bfloat16* __restrict__ H,
                              __nv_bfloat16* __restrict__ M,
                              __nv_bfloat16* __restrict__ L) {
    int i = blockIdx.x * 256 + threadIdx.x;
    float2 v = ((const float2*)X)[i];
    __nv_bfloat162 h2, m2, l2;
    {
        float x = v.x;
        __nv_bfloat16 h = __float2bfloat16(x);
        float r = x - __bfloat162float(h);
        __nv_bfloat16 m = __float2bfloat16(r);
        r -= __bfloat162float(m);
        h2.x = h; m2.x = m; l2.x = __float2bfloat16(r);
    }
    {
        float x = v.y;
        __nv_bfloat16 h = __float2bfloat16(x);
        float r = x - __bfloat162float(h);
        __nv_bfloat16 m = __float2bfloat16(r);
        r -= __bfloat162float(m);
        h2.y = h; m2.y = m; l2.y = __float2bfloat16(r);
    }
    ((__nv_bfloat162*)H)[i] = h2;
    ((__nv_bfloat162*)M)[i] = m2;
    ((__nv_bfloat162*)L)[i] = l2;
}

// ----------------------------------------------------------------------------
// Transpose + split W[k][n] -> WT{h,m,l}[n][k] bf16
// ----------------------------------------------------------------------------
__global__ void wsplit_kernel(const float* __restrict__ W,
                              __nv_bfloat16* __restrict__ H,
                              __nv_bfloat16* __restrict__ M,
                              __nv_bfloat16* __restrict__ L) {
    __shared__ float t[32][33];
    int n0 = blockIdx.x << 5, k0 = blockIdx.y << 5;
    int tx = threadIdx.x, ty = threadIdx.y;
#pragma unroll
    for (int i = 0; i < 4; i++)
        t[ty + i * 8][tx] = W[(size_t)(k0 + ty + i * 8) * CC + n0 + tx];
    __syncthreads();
#pragma unroll
    for (int i = 0; i < 4; i++) {
        int n = n0 + ty + i * 8;
        float x = t[tx][ty + i * 8];
        __nv_bfloat16 h = __float2bfloat16(x);
        float r = x - __bfloat162float(h);
        __nv_bfloat16 m = __float2bfloat16(r);
        r -= __bfloat162float(m);
        size_t o = (size_t)n * CC + k0 + tx;
        H[o] = h; M[o] = m; L[o] = __float2bfloat16(r);
    }
}

// ----------------------------------------------------------------------------
// Tensor-core GEMM via mma.sync bf16x3 (emulated fp32):
// Co[4096,1024] = A @ B^T + bias. A splits [M][K], B(=W^T) splits [N][K].
// Block 128x128, BK=32, 8 warps (2x4), warp tile 64x32 (4x4 m16n8k16 atoms).
// 6 split-products: hh, hm, mh, mm, hl, lh (error ~2^-24).
// smem rows have 40-elem (80B) stride -> conflict-free ldmatrix.
// ----------------------------------------------------------------------------
#define ASTRIDE 40
#define SPLITB (2 * 128 * ASTRIDE * 2)   // bytes per split (both buffers)
#define BUFB   (128 * ASTRIDE * 2)       // bytes per buffer

__global__ void __launch_bounds__(256, 1)
tc_gemm_kernel(const __nv_bfloat16* __restrict__ Ah,
               const __nv_bfloat16* __restrict__ Am,
               const __nv_bfloat16* __restrict__ Al,
               const __nv_bfloat16* __restrict__ Bh,
               const __nv_bfloat16* __restrict__ Bm,
               const __nv_bfloat16* __restrict__ Bl,
               const float* __restrict__ bias, float* __restrict__ Co) {
    extern __shared__ __align__(16) __nv_bfloat16 smb[];
    __nv_bfloat16* sB = smb + 3 * 2 * 128 * ASTRIDE;
    const u32 sAu = smem_u32(smb);
    const u32 sBu = smem_u32(sB);

    const int tid = threadIdx.x;
    const int wid = tid >> 5, lane = tid & 31;
    const int wm = wid >> 2, wn = wid & 3;        // warps 2 (m) x 4 (n)
    const int m0 = blockIdx.y << 7, n0 = blockIdx.x << 7;

    const __nv_bfloat16* Asrc[3] = {Ah, Am, Al};
    const __nv_bfloat16* Bsrc[3] = {Bh, Bm, Bl};

    float acc[4][4][4];
#pragma unroll
    for (int i = 0; i < 4; i++)
#pragma unroll
        for (int j = 0; j < 4; j++)
#pragma unroll
            for (int r = 0; r < 4; r++) acc[i][j][r] = 0.f;

    // cp.async coords (2 x 16B per split per tensor per thread)
    const int ldr0 = tid >> 2, ldk0 = (tid & 3) << 3;
    const int ldr1 = (tid + 256) >> 2, ldk1 = ((tid + 256) & 3) << 3;

    // ldmatrix per-lane offsets
    const u32 aRowB = (u32)(((lane & 7) + ((lane >> 3) & 1) * 8) * (ASTRIDE * 2));
    const u32 aKB   = (u32)(((lane >> 4) & 1) * 16);
    const u32 bRowB = (u32)(((lane & 7) + ((lane >> 4) & 1) * 8) * (ASTRIDE * 2));
    const u32 bKB   = (u32)(((lane >> 3) & 1) * 16);

#define ISSUE_CHUNK(c, buf)                                                     \
    do {                                                                        \
        _Pragma("unroll")                                                       \
        for (int t_ = 0; t_ < 3; t_++) {                                        \
            const __nv_bfloat16* ga = Asrc[t_] + (size_t)(m0 + ldr0) * CC +     \
                                      (c) * 32 + ldk0;                          \
            const __nv_bfloat16* ga1 = Asrc[t_] + (size_t)(m0 + ldr1) * CC +    \
                                       (c) * 32 + ldk1;                         \
            const __nv_bfloat16* gb = Bsrc[t_] + (size_t)(n0 + ldr0) * CC +     \
                                      (c) * 32 + ldk0;                          \
            const __nv_bfloat16* gb1 = Bsrc[t_] + (size_t)(n0 + ldr1) * CC +    \
                                       (c) * 32 + ldk1;                         \
            u32 d0 = (u32)(t_ * SPLITB + (buf) * BUFB +                         \
                           (ldr0 * ASTRIDE + ldk0) * 2);                        \
            u32 d1 = (u32)(t_ * SPLITB + (buf) * BUFB +                         \
                           (ldr1 * ASTRIDE + ldk1) * 2);                        \
            cpasync16(sAu + d0, ga);                                            \
            cpasync16(sAu + d1, ga1);                                           \
            cpasync16(sBu + d0, gb);                                            \
            cpasync16(sBu + d1, gb1);                                           \
        }                                                                       \
        cpcommit();                                                             \
    } while (0)

    ISSUE_CHUNK(0, 0);

    for (int c = 0; c < 32; c++) {
        const int buf = c & 1;
        cpwait0();
        __syncthreads();
        if (c + 1 < 32) ISSUE_CHUNK(c + 1, buf ^ 1);

#pragma unroll
        for (int ks = 0; ks < 2; ks++) {
            // A fragments: 3 splits x 4 m-atoms x 4 regs
            u32 af[3][4][4];
#pragma unroll
            for (int t = 0; t < 3; t++)
#pragma unroll
                for (int mi = 0; mi < 4; mi++) {
                    u32 addr = sAu + (u32)(t * SPLITB + buf * BUFB) +
                               (u32)((wm * 64 + mi * 16) * (ASTRIDE * 2)) +
                               aRowB + (u32)(ks * 32) + aKB;
                    ldsm_x4(af[t][mi][0], af[t][mi][1], af[t][mi][2],
                            af[t][mi][3], addr);
                }
            // B splits in turn: Bh -> {Ah,Am,Al}; Bm -> {Ah,Am}; Bl -> {Ah}
#pragma unroll
            for (int bt = 0; bt < 3; bt++) {
                u32 bfr[2][4];
#pragma unroll
                for (int np = 0; np < 2; np++) {
                    u32 addr = sBu + (u32)(bt * SPLITB + buf * BUFB) +
                               (u32)((wn * 32 + np * 16) * (ASTRIDE * 2)) +
                               bRowB + (u32)(ks * 32) + bKB;
                    ldsm_x4(bfr[np][0], bfr[np][1], bfr[np][2], bfr[np][3],
                            addr);
                }
                const int nA = (bt == 0) ? 3 : (bt == 1) ? 2 : 1;
#pragma unroll
                for (int ia = 0; ia < 3; ia++) {
                    if (ia >= nA) break;
#pragma unroll
                    for (int mi = 0; mi < 4; mi++)
#pragma unroll
                        for (int ni = 0; ni < 4; ni++)
                            mma_bf16(acc[mi][ni], af[ia][mi],
                                     &bfr[ni >> 1][(ni & 1) * 2]);
                }
            }
        }
        __syncthreads();
    }

    // epilogue: acc layout per m16n8k16 -> rows (g, g+8), cols (2q, 2q+1)
    const int grp = lane >> 2, qd = lane & 3;
#pragma unroll
    for (int mi = 0; mi < 4; mi++) {
#pragma unroll
        for (int ni = 0; ni < 4; ni++) {
            int row = m0 + wm * 64 + mi * 16 + grp;
            int col = n0 + wn * 32 + ni * 8 + qd * 2;
            float b0 = bias[col], b1 = bias[col + 1];
            float2 o0 = make_float2(acc[mi][ni][0] + b0, acc[mi][ni][1] + b1);
            float2 o1 = make_float2(acc[mi][ni][2] + b0, acc[mi][ni][3] + b1);
            *(float2*)&Co[(size_t)row * CC + col] = o0;
            *(float2*)&Co[(size_t)(row + 8) * CC + col] = o1;
        }
    }
}

// ----------------------------------------------------------------------------
// Batched FFT: one block per (tensor, b, h, 8-dim group). All three tensors
// (Q, K, V) handled by one launch; twiddles shared across the 8 columns.
// ----------------------------------------------------------------------------
#define FSTR 9
__global__ void __launch_bounds__(256, 1)
fft_filter_kernel(const float* __restrict__ inQ, const float* __restrict__ inK,
                  const float* __restrict__ inV,
                  float* __restrict__ oQr, float* __restrict__ oQi,
                  float* __restrict__ oKr, float* __restrict__ oKi,
                  float* __restrict__ oVr,
                  const float* __restrict__ fd,
                  const float* __restrict__ alpha,
                  const float* __restrict__ fas) {
    extern __shared__ __align__(16) float2 sh[];   // sh[t*FSTR + c], c<8
    const int dg = blockIdx.x;          // d-group 0..7
    const int which = blockIdx.y >> 4;  // 0=Q 1=K 2=V
    const int h = blockIdx.y & 15;
    const int b = blockIdx.z;
    const float* in = (which == 0) ? inQ : (which == 1) ? inK : inV;
    float* outRe = (which == 0) ? oQr : (which == 1) ? oKr : oVr;
    float* outIm = (which == 0) ? oQi : (which == 1) ? oKi : (float*)0;

    const int col0 = h * HDIM + dg * 8;
    const float* src = in + (size_t)b * TT * CC + col0;
    const int tid = threadIdx.x;

#pragma unroll
    for (int i = 0; i < 32; i++) {
        int e = tid + i * 256;
        int t = e >> 2, pr = e & 3;
        float2 v = *(const float2*)&src[(size_t)t * CC + pr * 2];
        unsigned r = __brev((unsigned)t) >> (32 - LOG2T);
        sh[r * FSTR + pr * 2]     = make_float2(v.x, 0.f);
        sh[r * FSTR + pr * 2 + 1] = make_float2(v.y, 0.f);
    }
    __syncthreads();

    for (int st = 1; st <= LOG2T; st++) {
        const int half = 1 << (st - 1);
        const float wstep = -6.283185307179586f / (float)(half * 2);
#pragma unroll
        for (int w = 0; w < 4; w++) {
            int idx = tid + w * 256;
            int pos = idx & (half - 1);
            int grp = idx >> (st - 1);
            int i0 = (grp << st) + pos;
            int i1 = i0 + half;
            float sn, cs;
            __sincosf(wstep * (float)pos, &sn, &cs);
            float2* p0 = &sh[i0 * FSTR];
            float2* p1 = &sh[i1 * FSTR];
#pragma unroll
            for (int c = 0; c < 8; c++) {
                float2 u = p0[c], v = p1[c];
                float tr = cs * v.x - sn * v.y;
                float ti = cs * v.y + sn * v.x;
                p0[c] = make_float2(u.x + tr, u.y + ti);
                p1[c] = make_float2(u.x - tr, u.y - ti);
            }
        }
        __syncthreads();
    }

    const float aal = alpha[0] + fas[0] * (fd[0] - 1.5f);
    const size_t obase = ((size_t)(b * HH + h)) * TT * HDIM + dg * 8;
#pragma unroll
    for (int i = 0; i < 8; i++) {
        int t = tid + i * 256;
        float fr = (float)(t < TT / 2 ? t : t - TT) * (1.0f / (float)TT);
        float phase = aal * atanf(logf(fabsf(fr) + 1e-10f));
        float sp, cp;
        sincosf(phase, &sp, &cp);
        const float2* p = &sh[t * FSTR];
        float re[8], im[8];
#pragma unroll
        for (int c = 0; c < 8; c++) {
            float2 X = p[c];
            re[c] = X.x * cp - X.y * sp;
            im[c] = X.x * sp + X.y * cp;
        }
        size_t o = obase + (size_t)t * HDIM;
        *(float4*)&outRe[o]     = make_float4(re[0], re[1], re[2], re[3]);
        *(float4*)&outRe[o + 4] = make_float4(re[4], re[5], re[6], re[7]);
        if (outIm) {
            *(float4*)&outIm[o]     = make_float4(im[0], im[1], im[2], im[3]);
            *(float4*)&outIm[o + 4] = make_float4(im[4], im[5], im[6], im[7]);
        }
    }
}

// ----------------------------------------------------------------------------
// Flash attention per (b,h). 128x128 tiles, 512 threads, column-packed f32x2:
// K/V operand pairs come straight from smem as u64 (no dup2); only Q/P
// broadcasts use dup2. Ki stored NEGATED; P aliases Kr+Ki smem.
// ----------------------------------------------------------------------------
__global__ void __launch_bounds__(512, 1)
attn_kernel(const float* __restrict__ Qr, const float* __restrict__ Qi,
            const float* __restrict__ Kr, const float* __restrict__ Ki,
            const float* __restrict__ Vr, float* __restrict__ Ao) {
    extern __shared__ __align__(16) float smbuf[];
    float* sQr = smbuf;                 // [d=64][132]
    float* sQi = sQr + 64 * 132;
    float* sKr = sQi + 64 * 132;        // [d=64][132]
    float* sKi = sKr + 64 * 132;        // holds -Ki
    float* sV  = sKi + 64 * 132;        // [s=128][68]
    float* sP  = sKr;                   // [t=128][132], aliases Kr+Ki

    const int tid = threadIdx.x;
    const int ty = tid >> 4, tx = tid & 15;   // ty 0..31, tx 0..15
    const int t0 = blockIdx.x << 7;
    const int h = blockIdx.y, b = blockIdx.z;
    const size_t base = ((size_t)(b * HH + h)) * TT * HDIM;
    const int r0 = ty << 2;                   // 4 rows per thread
    const int c0 = tx << 2;                   // 4+4 cols per thread

    // load Q tile (transposed into [d][t])
#pragma unroll
    for (int i = 0; i < 4; i++) {
        int e = tid + i * 512;          // 0..2047
        int r = e >> 4, c4 = (e & 15) << 2;
        size_t g = base + (size_t)(t0 + r) * HDIM + c4;
        float4 qr = *(const float4*)&Qr[g];
        float4 qi = *(const float4*)&Qi[g];
        sQr[(c4 + 0) * 132 + r] = qr.x;
        sQr[(c4 + 1) * 132 + r] = qr.y;
        sQr[(c4 + 2) * 132 + r] = qr.z;
        sQr[(c4 + 3) * 132 + r] = qr.w;
        sQi[(c4 + 0) * 132 + r] = qi.x;
        sQi[(c4 + 1) * 132 + r] = qi.y;
        sQi[(c4 + 2) * 132 + r] = qi.z;
        sQi[(c4 + 3) * 132 + r] = qi.w;
    }

    float m[4], l[4];
    u64 acc2[4][2];                     // [row][col-pair]
#pragma unroll
    for (int i = 0; i < 4; i++) { m[i] = -INFINITY; l[i] = 0.f; }
#pragma unroll
    for (int i = 0; i < 4; i++) { acc2[i][0] = 0ull; acc2[i][1] = 0ull; }

    for (int s0 = 0; s0 < TT; s0 += 128) {
        __syncthreads();  // P/V consumed (and Q visible on first iter)
#pragma unroll
        for (int i = 0; i < 4; i++) {
            int e = tid + i * 512;
            int r = e >> 4, c4 = (e & 15) << 2;
            size_t g = base + (size_t)(s0 + r) * HDIM + c4;
            float4 kr = *(const float4*)&Kr[g];
            float4 ki = *(const float4*)&Ki[g];
            sKr[(c4 + 0) * 132 + r] = kr.x;
            sKr[(c4 + 1) * 132 + r] = kr.y;
            sKr[(c4 + 2) * 132 + r] = kr.z;
            sKr[(c4 + 3) * 132 + r] = kr.w;
            sKi[(c4 + 0) * 132 + r] = -ki.x;
            sKi[(c4 + 1) * 132 + r] = -ki.y;
            sKi[(c4 + 2) * 132 + r] = -ki.z;
            sKi[(c4 + 3) * 132 + r] = -ki.w;
            *(float4*)&sV[r * 68 + c4] = *(const float4*)&Vr[g];
        }
        __syncthreads();

        // ---- S tile: [4 rows][4 col-pairs]; K pairs direct from smem ----
        u64 S2[4][4];
#pragma unroll
        for (int i = 0; i < 4; i++)
#pragma unroll
            for (int j = 0; j < 4; j++) S2[i][j] = 0ull;

#pragma unroll 4
        for (int d = 0; d < 64; d++) {
            float4 q4 = *(const float4*)&sQr[d * 132 + r0];
            float4 p4 = *(const float4*)&sQi[d * 132 + r0];
            ulonglong2 K0 = *(const ulonglong2*)&sKr[d * 132 + c0];
            ulonglong2 K1 = *(const ulonglong2*)&sKr[d * 132 + 64 + c0];
            ulonglong2 J0 = *(const ulonglong2*)&sKi[d * 132 + c0];
            ulonglong2 J1 = *(const ulonglong2*)&sKi[d * 132 + 64 + c0];
            u64 kp[4] = {K0.x, K0.y, K1.x, K1.y};
            u64 jp[4] = {J0.x, J0.y, J1.x, J1.y};
            float qv[4] = {q4.x, q4.y, q4.z, q4.w};
            float pv_[4] = {p4.x, p4.y, p4.z, p4.w};
#pragma unroll
            for (int i = 0; i < 4; i++) {
                u64 qd = dup2(qv[i]);
                u64 pd = dup2(pv_[i]);
#pragma unroll
                for (int cp = 0; cp < 4; cp++) {
                    fma2(S2[i][cp], qd, kp[cp]);
                    fma2(S2[i][cp], pd, jp[cp]);
                }
            }
        }
        __syncthreads();  // all K reads done before P overwrites that smem

        float S[4][8];
#pragma unroll
        for (int i = 0; i < 4; i++)
#pragma unroll
            for (int cp = 0; cp < 4; cp++)
                upk2(S[i][2 * cp], S[i][2 * cp + 1], S2[i][cp]);

        // ---- online softmax; write P into aliased smem ----
        float corr[4];
#pragma unroll
        for (int i = 0; i < 4; i++) {
            float mx = S[i][0];
#pragma unroll
            for (int j = 1; j < 8; j++) mx = fmaxf(mx, S[i][j]);
            mx *= 0.125f;
#pragma unroll
            for (int o = 8; o >= 1; o >>= 1)
                mx = fmaxf(mx, __shfl_xor_sync(0xffffffffu, mx, o));
            float mn = fmaxf(m[i], mx);
            corr[i] = __expf(m[i] - mn);
            float ps = 0.f;
            float pv[8];
#pragma unroll
            for (int j = 0; j < 8; j++) {
                float p = __expf(S[i][j] * 0.125f - mn);
                pv[j] = p;
                ps += p;
            }
            *(float4*)&sP[(r0 + i) * 132 + c0] =
                make_float4(pv[0], pv[1], pv[2], pv[3]);
            *(float4*)&sP[(r0 + i) * 132 + 64 + c0] =
                make_float4(pv[4], pv[5], pv[6], pv[7]);
#pragma unroll
            for (int o = 8; o >= 1; o >>= 1)
                ps += __shfl_xor_sync(0xffffffffu, ps, o);
            l[i] = l[i] * corr[i] + ps;
            m[i] = mn;
        }
#pragma unroll
        for (int i = 0; i < 4; i++) {
            u64 cd = dup2(corr[i]);
            u64 t0r, t1r;
            mul2(t0r, acc2[i][0], cd);
            mul2(t1r, acc2[i][1], cd);
            acc2[i][0] = t0r;
            acc2[i][1] = t1r;
        }
        __syncthreads();

        // ---- O += P @ V: V pairs direct from smem, P scalars dup'd ----
#pragma unroll 4
        for (int s = 0; s < 128; s += 2) {
            ulonglong2 V0 = *(const ulonglong2*)&sV[s * 68 + c0];
            ulonglong2 V1 = *(const ulonglong2*)&sV[(s + 1) * 68 + c0];
#pragma unroll
            for (int i = 0; i < 4; i++) {
                float2 pp = *(const float2*)&sP[(r0 + i) * 132 + s];
                u64 pd0 = dup2(pp.x);
                u64 pd1 = dup2(pp.y);
                fma2(acc2[i][0], pd0, V0.x);
                fma2(acc2[i][1], pd0, V0.y);
                fma2(acc2[i][0], pd1, V1.x);
                fma2(acc2[i][1], pd1, V1.y);
            }
        }
    }

    // epilogue: normalize and write [b, t, h*64+d]
#pragma unroll
    for (int i = 0; i < 4; i++) {
        float a0, a1, a2, a3;
        upk2(a0, a1, acc2[i][0]);
        upk2(a2, a3, acc2[i][1]);
        float inv = 1.f / l[i];
        float4 o = make_float4(a0 * inv, a1 * inv, a2 * inv, a3 * inv);
        size_t off = ((size_t)(b * TT + t0 + r0 + i)) * CC + h * HDIM + c0;
        *(float4*)&Ao[off] = o;
    }
}

// ----------------------------------------------------------------------------
// Final energy ratio: out = Y * (inE / (||Y row|| + 1e-8)) * energy_normalizer
// ----------------------------------------------------------------------------
__global__ void finalize_kernel(const float* __restrict__ Y,
                                const float* __restrict__ enorm,
                                float* __restrict__ out) {
    int row = blockIdx.x;
    const float* yr = Y + (size_t)row * CC;
    float s = 0.f;
    for (int c = threadIdx.x; c < CC; c += 256) {
        float v = yr[c];
        s += v * v;
    }
    float tot = blockReduceSum256(s);
    __shared__ float ratio;
    if (threadIdx.x == 0)
        ratio = g_inE[row] / (sqrtf(tot) + 1e-8f) * enorm[0];
    __syncthreads();
    for (int c = threadIdx.x; c < CC; c += 256)
        out[(size_t)row * CC + c] = yr[c] * ratio;
}

// ----------------------------------------------------------------------------
// Launch
// ----------------------------------------------------------------------------
extern "C" void kernel_launch(void* const* d_in, const int* in_sizes, int n_in,
                              void* d_out, int out_size) {
    const float* x      = (const float*)d_in[0];
    const float* fd     = (const float*)d_in[1];
    const float* wq     = (const float*)d_in[2];
    const float* bq     = (const float*)d_in[3];
    const float* wk     = (const float*)d_in[4];
    const float* bk     = (const float*)d_in[5];
    const float* wv     = (const float*)d_in[6];
    const float* bv     = (const float*)d_in[7];
    const float* wo     = (const float*)d_in[8];
    const float* bo     = (const float*)d_in[9];
    const float* alpha  = (const float*)d_in[10];
    const float* fas    = (const float*)d_in[11];
    const float* enorm  = (const float*)d_in[12];
    float* out = (float*)d_out;

    float *q, *k, *v, *qr, *qi, *kr, *ki, *vr, *att, *y;
    __nv_bfloat16 *xh, *xm, *xl, *wt;
    cudaGetSymbolAddress((void**)&q,  g_q);
    cudaGetSymbolAddress((void**)&k,  g_k);
    cudaGetSymbolAddress((void**)&v,  g_v);
    cudaGetSymbolAddress((void**)&qr, g_qr);
    cudaGetSymbolAddress((void**)&qi, g_qi);
    cudaGetSymbolAddress((void**)&kr, g_kr);
    cudaGetSymbolAddress((void**)&ki, g_ki);
    cudaGetSymbolAddress((void**)&vr, g_vr);
    cudaGetSymbolAddress((void**)&att, g_att);
    cudaGetSymbolAddress((void**)&y,  g_y);
    cudaGetSymbolAddress((void**)&xh, g_xh);
    cudaGetSymbolAddress((void**)&xm, g_xm);
    cudaGetSymbolAddress((void**)&xl, g_xl);
    cudaGetSymbolAddress((void**)&wt, g_wt);
    const size_t WSZ = (size_t)CC * CC;

    // input energies
    energy_in_kernel<<<BT, 256>>>(x);

    // prep: split x, transpose+split all 4 weights
    asplit_kernel<<<BT * CC / 512, 256>>>(x, xh, xm, xl);
    dim3 wg(32, 32), wb(32, 8);
    wsplit_kernel<<<wg, wb>>>(wq, wt + 0 * WSZ, wt + 1 * WSZ, wt + 2 * WSZ);
    wsplit_kernel<<<wg, wb>>>(wk, wt + 3 * WSZ, wt + 4 * WSZ, wt + 5 * WSZ);
    wsplit_kernel<<<wg, wb>>>(wv, wt + 6 * WSZ, wt + 7 * WSZ, wt + 8 * WSZ);
    wsplit_kernel<<<wg, wb>>>(wo, wt + 9 * WSZ, wt + 10 * WSZ, wt + 11 * WSZ);

    // QKV projections on tensor cores (mma.sync bf16x3)
    static const int kTcSmem = 2 * 3 * 2 * 128 * ASTRIDE * (int)sizeof(__nv_bfloat16);
    cudaFuncSetAttribute(tc_gemm_kernel,
                         cudaFuncAttributeMaxDynamicSharedMemorySize, kTcSmem);
    dim3 gg(CC / 128, BT / 128);
    tc_gemm_kernel<<<gg, 256, kTcSmem>>>(xh, xm, xl,
                                         wt + 0 * WSZ, wt + 1 * WSZ, wt + 2 * WSZ,
                                         bq, q);
    tc_gemm_kernel<<<gg, 256, kTcSmem>>>(xh, xm, xl,
                                         wt + 3 * WSZ, wt + 4 * WSZ, wt + 5 * WSZ,
                                         bk, k);
    tc_gemm_kernel<<<gg, 256, kTcSmem>>>(xh, xm, xl,
                                         wt + 6 * WSZ, wt + 7 * WSZ, wt + 8 * WSZ,
                                         bv, v);

    // FFT + spectral filter, all three tensors in one launch
    static const int kFftSmem = TT * FSTR * (int)sizeof(float2);  // 147456
    cudaFuncSetAttribute(fft_filter_kernel,
                         cudaFuncAttributeMaxDynamicSharedMemorySize, kFftSmem);
    dim3 gf(HDIM / 8, HH * 3, BB);
    fft_filter_kernel<<<gf, 256, kFftSmem>>>(q, k, v, qr, qi, kr, ki, vr,
                                             fd, alpha, fas);

    // attention: smem = (4*64*132 + 128*68) floats = 169,984 B
    static const int kAttnSmem = (4 * 64 * 132 + 128 * 68) * (int)sizeof(float);
    cudaFuncSetAttribute(attn_kernel, cudaFuncAttributeMaxDynamicSharedMemorySize,
                         kAttnSmem);
    dim3 ga(TT / 128, HH, BB);
    attn_kernel<<<ga, 512, kAttnSmem>>>(qr, qi, kr, ki, vr, att);

    // output projection (split att, reuse x-split buffers)
    asplit_kernel<<<BT * CC / 512, 256>>>(att, xh, xm, xl);
    tc_gemm_kernel<<<gg, 256, kTcSmem>>>(xh, xm, xl,
                                         wt + 9 * WSZ, wt + 10 * WSZ, wt + 11 * WSZ,
                                         bo, y);

    // energy-ratio epilogue
    finalize_kernel<<<BT, 256>>>(y, enorm, out);
}

// round 10
// speedup vs baseline: 1.2958x; 1.0142x over previous
#include <cuda_runtime.h>
#include <cuda_bf16.h>
#include <math.h>
#include <cstdint>

// Problem constants
#define BB 2
#define TT 2048
#define CC 1024
#define HH 16
#define HDIM 64
#define BT (BB * TT)      // 4096 rows
#define LOG2T 11

typedef unsigned long long u64;
typedef unsigned int u32;

// ---------------------------------------------------------------------------
// Packed f32x2 helpers (Blackwell sm_103a)
// ---------------------------------------------------------------------------
__device__ __forceinline__ u64 pk2(float lo, float hi) {
    u64 r;
    asm("mov.b64 %0, {%1, %2};" : "=l"(r) : "f"(lo), "f"(hi));
    return r;
}
__device__ __forceinline__ u64 dup2(float v) { return pk2(v, v); }
__device__ __forceinline__ void upk2(float& lo, float& hi, u64 v) {
    asm("mov.b64 {%0, %1}, %2;" : "=f"(lo), "=f"(hi) : "l"(v));
}
__device__ __forceinline__ void fma2(u64& d, u64 a, u64 b) {
    asm("fma.rn.f32x2 %0, %1, %2, %0;" : "+l"(d) : "l"(a), "l"(b));
}
__device__ __forceinline__ void mul2(u64& d, u64 a, u64 b) {
    asm("mul.rn.f32x2 %0, %1, %2;" : "=l"(d) : "l"(a), "l"(b));
}

// ---------------------------------------------------------------------------
// mma.sync / ldmatrix / cp.async helpers (compute_103-legal PTX)
// ---------------------------------------------------------------------------
__device__ __forceinline__ u32 smem_u32(const void* p) {
    u32 a;
    asm("{ .reg .u64 t; cvta.to.shared.u64 t, %1; cvt.u32.u64 %0, t; }"
        : "=r"(a) : "l"(p));
    return a;
}
__device__ __forceinline__ void cpasync16(u32 smem_dst, const void* gptr) {
    asm volatile("cp.async.ca.shared.global [%0], [%1], 16;"
                 :: "r"(smem_dst), "l"(gptr));
}
__device__ __forceinline__ void cpcommit() {
    asm volatile("cp.async.commit_group;");
}
__device__ __forceinline__ void cpwait0() {
    asm volatile("cp.async.wait_group 0;");
}
__device__ __forceinline__ void ldsm_x4(u32& r0, u32& r1, u32& r2, u32& r3,
                                        u32 addr) {
    asm volatile("ldmatrix.sync.aligned.m8n8.x4.shared.b16 {%0,%1,%2,%3}, [%4];"
                 : "=r"(r0), "=r"(r1), "=r"(r2), "=r"(r3) : "r"(addr));
}
__device__ __forceinline__ void mma_bf16(float* c, const u32* a, const u32* b) {
    asm volatile(
        "mma.sync.aligned.m16n8k16.row.col.f32.bf16.bf16.f32 "
        "{%0,%1,%2,%3}, {%4,%5,%6,%7}, {%8,%9}, {%0,%1,%2,%3};"
        : "+f"(c[0]), "+f"(c[1]), "+f"(c[2]), "+f"(c[3])
        : "r"(a[0]), "r"(a[1]), "r"(a[2]), "r"(a[3]), "r"(b[0]), "r"(b[1]));
}

// ----------------------------------------------------------------------------
// Device scratch (static; no allocations allowed)
// ----------------------------------------------------------------------------
static __device__ float g_q[BT * CC];
static __device__ float g_k[BT * CC];
static __device__ float g_v[BT * CC];
static __device__ float g_qr[BT * CC];
static __device__ float g_qi[BT * CC];
static __device__ float g_kr[BT * CC];
static __device__ float g_ki[BT * CC];
static __device__ float g_vr[BT * CC];
static __device__ float g_y[BT * CC];
static __device__ float g_inE[BT];
// bf16x3 splits
static __device__ __nv_bfloat16 g_xh[BT * CC];
static __device__ __nv_bfloat16 g_xm[BT * CC];
static __device__ __nv_bfloat16 g_xl[BT * CC];
static __device__ __nv_bfloat16 g_wt[12 * CC * CC];   // 4 weights x {h,m,l}, [N][K]

// ----------------------------------------------------------------------------
// Reductions
// ----------------------------------------------------------------------------
__device__ __forceinline__ float blockReduceSum256(float v) {
    __shared__ float red[8];
    int lane = threadIdx.x & 31;
    int w = threadIdx.x >> 5;
#pragma unroll
    for (int o = 16; o >= 1; o >>= 1)
        v += __shfl_xor_sync(0xffffffffu, v, o);
    if (lane == 0) red[w] = v;
    __syncthreads();
    if (w == 0) {
        v = (lane < 8) ? red[lane] : 0.f;
#pragma unroll
        for (int o = 4; o >= 1; o >>= 1)
            v += __shfl_xor_sync(0xffffffffu, v, o);
    }
    return v;  // valid in thread 0
}

// ----------------------------------------------------------------------------
// Fused: input energy ||x[row,:]|| + bf16x3 split of x (one pass over x)
// ----------------------------------------------------------------------------
__global__ void energy_split_kernel(const float* __restrict__ x,
                                    __nv_bfloat16* __restrict__ H,
                                    __nv_bfloat16* __restrict__ M,
                                    __nv_bfloat16* __restrict__ L) {
    int row = blockIdx.x;
    const float* xr = x + (size_t)row * CC;
    float s = 0.f;
    for (int c = threadIdx.x; c < CC; c += 256) {
        float v = xr[c];
        s += v * v;
        __nv_bfloat16 h = __float2bfloat16(v);
        float r = v - __bfloat162float(h);
        __nv_bfloat16 m = __float2bfloat16(r);
        r -= __bfloat162float(m);
        size_t o = (size_t)row * CC + c;
        H[o] = h; M[o] = m; L[o] = __float2bfloat16(r);
    }
    float tot = blockReduceSum256(s);
    if (threadIdx.x == 0) g_inE[row] = sqrtf(tot);
}

// ----------------------------------------------------------------------------
// Transpose + split W[k][n] -> WT{h,m,l}[n][k] bf16
// ----------------------------------------------------------------------------
__global__ void wsplit_kernel(const float* __restrict__ W,
                              __nv_bfloat16* __restrict__ H,
                              __nv_bfloat16* __restrict__ M,
                              __nv_bfloat16* __restrict__ L) {
    __shared__ float t[32][33];
    int n0 = blockIdx.x << 5, k0 = blockIdx.y << 5;
    int tx = threadIdx.x, ty = threadIdx.y;
#pragma unroll
    for (int i = 0; i < 4; i++)
        t[ty + i * 8][tx] = W[(size_t)(k0 + ty + i * 8) * CC + n0 + tx];
    __syncthreads();
#pragma unroll
    for (int i = 0; i < 4; i++) {
        int n = n0 + ty + i * 8;
        float x = t[tx][ty + i * 8];
        __nv_bfloat16 h = __float2bfloat16(x);
        float r = x - __bfloat162float(h);
        __nv_bfloat16 m = __float2bfloat16(r);
        r -= __bfloat162float(m);
        size_t o = (size_t)n * CC + k0 + tx;
        H[o] = h; M[o] = m; L[o] = __float2bfloat16(r);
    }
}

// ----------------------------------------------------------------------------
// Tensor-core GEMM via mma.sync bf16x3 (emulated fp32):
// Co[4096,1024] = A @ B^T + bias. A splits [M][K], B(=W^T) splits [N][K].
// Block 128x128, BK=32, 8 warps (2x4), warp tile 64x32 (4x4 m16n8k16 atoms).
// 6 split-products: hh, hm, mh, mm, hl, lh (error ~2^-24).
// ----------------------------------------------------------------------------
#define ASTRIDE 40
#define SPLITB (2 * 128 * ASTRIDE * 2)   // bytes per split (both buffers)
#define BUFB   (128 * ASTRIDE * 2)       // bytes per buffer

__global__ void __launch_bounds__(256, 1)
tc_gemm_kernel(const __nv_bfloat16* __restrict__ Ah,
               const __nv_bfloat16* __restrict__ Am,
               const __nv_bfloat16* __restrict__ Al,
               const __nv_bfloat16* __restrict__ Bh,
               const __nv_bfloat16* __restrict__ Bm,
               const __nv_bfloat16* __restrict__ Bl,
               const float* __restrict__ bias, float* __restrict__ Co) {
    extern __shared__ __align__(16) __nv_bfloat16 smb[];
    __nv_bfloat16* sB = smb + 3 * 2 * 128 * ASTRIDE;
    const u32 sAu = smem_u32(smb);
    const u32 sBu = smem_u32(sB);

    const int tid = threadIdx.x;
    const int wid = tid >> 5, lane = tid & 31;
    const int wm = wid >> 2, wn = wid & 3;        // warps 2 (m) x 4 (n)
    const int m0 = blockIdx.y << 7, n0 = blockIdx.x << 7;

    const __nv_bfloat16* Asrc[3] = {Ah, Am, Al};
    const __nv_bfloat16* Bsrc[3] = {Bh, Bm, Bl};

    float acc[4][4][4];
#pragma unroll
    for (int i = 0; i < 4; i++)
#pragma unroll
        for (int j = 0; j < 4; j++)
#pragma unroll
            for (int r = 0; r < 4; r++) acc[i][j][r] = 0.f;

    const int ldr0 = tid >> 2, ldk0 = (tid & 3) << 3;
    const int ldr1 = (tid + 256) >> 2, ldk1 = ((tid + 256) & 3) << 3;

    const u32 aRowB = (u32)(((lane & 7) + ((lane >> 3) & 1) * 8) * (ASTRIDE * 2));
    const u32 aKB   = (u32)(((lane >> 4) & 1) * 16);
    const u32 bRowB = (u32)(((lane & 7) + ((lane >> 4) & 1) * 8) * (ASTRIDE * 2));
    const u32 bKB   = (u32)(((lane >> 3) & 1) * 16);

#define ISSUE_CHUNK(c, buf)                                                     \
    do {                                                                        \
        _Pragma("unroll")                                                       \
        for (int t_ = 0; t_ < 3; t_++) {                                        \
            const __nv_bfloat16* ga = Asrc[t_] + (size_t)(m0 + ldr0) * CC +     \
                                      (c) * 32 + ldk0;                          \
            const __nv_bfloat16* ga1 = Asrc[t_] + (size_t)(m0 + ldr1) * CC +    \
                                       (c) * 32 + ldk1;                         \
            const __nv_bfloat16* gb = Bsrc[t_] + (size_t)(n0 + ldr0) * CC +     \
                                      (c) * 32 + ldk0;                          \
            const __nv_bfloat16* gb1 = Bsrc[t_] + (size_t)(n0 + ldr1) * CC +    \
                                       (c) * 32 + ldk1;                         \
            u32 d0 = (u32)(t_ * SPLITB + (buf) * BUFB +                         \
                           (ldr0 * ASTRIDE + ldk0) * 2);                        \
            u32 d1 = (u32)(t_ * SPLITB + (buf) * BUFB +                         \
                           (ldr1 * ASTRIDE + ldk1) * 2);                        \
            cpasync16(sAu + d0, ga);                                            \
            cpasync16(sAu + d1, ga1);                                           \
            cpasync16(sBu + d0, gb);                                            \
            cpasync16(sBu + d1, gb1);                                           \
        }                                                                       \
        cpcommit();                                                             \
    } while (0)

    ISSUE_CHUNK(0, 0);

    for (int c = 0; c < 32; c++) {
        const int buf = c & 1;
        cpwait0();
        __syncthreads();
        if (c + 1 < 32) ISSUE_CHUNK(c + 1, buf ^ 1);

#pragma unroll
        for (int ks = 0; ks < 2; ks++) {
            u32 af[3][4][4];
#pragma unroll
            for (int t = 0; t < 3; t++)
#pragma unroll
                for (int mi = 0; mi < 4; mi++) {
                    u32 addr = sAu + (u32)(t * SPLITB + buf * BUFB) +
                               (u32)((wm * 64 + mi * 16) * (ASTRIDE * 2)) +
                               aRowB + (u32)(ks * 32) + aKB;
                    ldsm_x4(af[t][mi][0], af[t][mi][1], af[t][mi][2],
                            af[t][mi][3], addr);
                }
#pragma unroll
            for (int bt = 0; bt < 3; bt++) {
                u32 bfr[2][4];
#pragma unroll
                for (int np = 0; np < 2; np++) {
                    u32 addr = sBu + (u32)(bt * SPLITB + buf * BUFB) +
                               (u32)((wn * 32 + np * 16) * (ASTRIDE * 2)) +
                               bRowB + (u32)(ks * 32) + bKB;
                    ldsm_x4(bfr[np][0], bfr[np][1], bfr[np][2], bfr[np][3],
                            addr);
                }
                const int nA = (bt == 0) ? 3 : (bt == 1) ? 2 : 1;
#pragma unroll
                for (int ia = 0; ia < 3; ia++) {
                    if (ia >= nA) break;
#pragma unroll
                    for (int mi = 0; mi < 4; mi++)
#pragma unroll
                        for (int ni = 0; ni < 4; ni++)
                            mma_bf16(acc[mi][ni], af[ia][mi],
                                     &bfr[ni >> 1][(ni & 1) * 2]);
                }
            }
        }
        __syncthreads();
    }

    const int grp = lane >> 2, qd = lane & 3;
#pragma unroll
    for (int mi = 0; mi < 4; mi++) {
#pragma unroll
        for (int ni = 0; ni < 4; ni++) {
            int row = m0 + wm * 64 + mi * 16 + grp;
            int col = n0 + wn * 32 + ni * 8 + qd * 2;
            float b0 = bias[col], b1 = bias[col + 1];
            float2 o0 = make_float2(acc[mi][ni][0] + b0, acc[mi][ni][1] + b1);
            float2 o1 = make_float2(acc[mi][ni][2] + b0, acc[mi][ni][3] + b1);
            *(float2*)&Co[(size_t)row * CC + col] = o0;
            *(float2*)&Co[(size_t)(row + 8) * CC + col] = o1;
        }
    }
}

// ----------------------------------------------------------------------------
// Batched FFT: one block per (tensor, b, h, 8-dim group). All three tensors
// (Q, K, V) handled by one launch; twiddles shared across the 8 columns.
// ----------------------------------------------------------------------------
#define FSTR 9
__global__ void __launch_bounds__(256, 1)
fft_filter_kernel(const float* __restrict__ inQ, const float* __restrict__ inK,
                  const float* __restrict__ inV,
                  float* __restrict__ oQr, float* __restrict__ oQi,
                  float* __restrict__ oKr, float* __restrict__ oKi,
                  float* __restrict__ oVr,
                  const float* __restrict__ fd,
                  const float* __restrict__ alpha,
                  const float* __restrict__ fas) {
    extern __shared__ __align__(16) float2 sh[];   // sh[t*FSTR + c], c<8
    const int dg = blockIdx.x;          // d-group 0..7
    const int which = blockIdx.y >> 4;  // 0=Q 1=K 2=V
    const int h = blockIdx.y & 15;
    const int b = blockIdx.z;
    const float* in = (which == 0) ? inQ : (which == 1) ? inK : inV;
    float* outRe = (which == 0) ? oQr : (which == 1) ? oKr : oVr;
    float* outIm = (which == 0) ? oQi : (which == 1) ? oKi : (float*)0;

    const int col0 = h * HDIM + dg * 8;
    const float* src = in + (size_t)b * TT * CC + col0;
    const int tid = threadIdx.x;

#pragma unroll
    for (int i = 0; i < 32; i++) {
        int e = tid + i * 256;
        int t = e >> 2, pr = e & 3;
        float2 v = *(const float2*)&src[(size_t)t * CC + pr * 2];
        unsigned r = __brev((unsigned)t) >> (32 - LOG2T);
        sh[r * FSTR + pr * 2]     = make_float2(v.x, 0.f);
        sh[r * FSTR + pr * 2 + 1] = make_float2(v.y, 0.f);
    }
    __syncthreads();

    for (int st = 1; st <= LOG2T; st++) {
        const int half = 1 << (st - 1);
        const float wstep = -6.283185307179586f / (float)(half * 2);
#pragma unroll
        for (int w = 0; w < 4; w++) {
            int idx = tid + w * 256;
            int pos = idx & (half - 1);
            int grp = idx >> (st - 1);
            int i0 = (grp << st) + pos;
            int i1 = i0 + half;
            float sn, cs;
            __sincosf(wstep * (float)pos, &sn, &cs);
            float2* p0 = &sh[i0 * FSTR];
            float2* p1 = &sh[i1 * FSTR];
#pragma unroll
            for (int c = 0; c < 8; c++) {
                float2 u = p0[c], v = p1[c];
                float tr = cs * v.x - sn * v.y;
                float ti = cs * v.y + sn * v.x;
                p0[c] = make_float2(u.x + tr, u.y + ti);
                p1[c] = make_float2(u.x - tr, u.y - ti);
            }
        }
        __syncthreads();
    }

    const float aal = alpha[0] + fas[0] * (fd[0] - 1.5f);
    const size_t obase = ((size_t)(b * HH + h)) * TT * HDIM + dg * 8;
#pragma unroll
    for (int i = 0; i < 8; i++) {
        int t = tid + i * 256;
        float fr = (float)(t < TT / 2 ? t : t - TT) * (1.0f / (float)TT);
        float phase = aal * atanf(logf(fabsf(fr) + 1e-10f));
        float sp, cp;
        sincosf(phase, &sp, &cp);
        const float2* p = &sh[t * FSTR];
        float re[8], im[8];
#pragma unroll
        for (int c = 0; c < 8; c++) {
            float2 X = p[c];
            re[c] = X.x * cp - X.y * sp;
            im[c] = X.x * sp + X.y * cp;
        }
        size_t o = obase + (size_t)t * HDIM;
        *(float4*)&outRe[o]     = make_float4(re[0], re[1], re[2], re[3]);
        *(float4*)&outRe[o + 4] = make_float4(re[4], re[5], re[6], re[7]);
        if (outIm) {
            *(float4*)&outIm[o]     = make_float4(im[0], im[1], im[2], im[3]);
            *(float4*)&outIm[o + 4] = make_float4(im[4], im[5], im[6], im[7]);
        }
    }
}

// ----------------------------------------------------------------------------
// Flash attention per (b,h). 128x128 tiles, 512 threads, column-packed f32x2.
// Epilogue writes the bf16x3 split of O directly (feeds the wo tc-GEMM),
// skipping the fp32 round-trip + separate split kernel.
// ----------------------------------------------------------------------------
__global__ void __launch_bounds__(512, 1)
attn_kernel(const float* __restrict__ Qr, const float* __restrict__ Qi,
            const float* __restrict__ Kr, const float* __restrict__ Ki,
            const float* __restrict__ Vr,
            __nv_bfloat16* __restrict__ Oh, __nv_bfloat16* __restrict__ Om,
            __nv_bfloat16* __restrict__ Ol) {
    extern __shared__ __align__(16) float smbuf[];
    float* sQr = smbuf;                 // [d=64][132]
    float* sQi = sQr + 64 * 132;
    float* sKr = sQi + 64 * 132;        // [d=64][132]
    float* sKi = sKr + 64 * 132;        // holds -Ki
    float* sV  = sKi + 64 * 132;        // [s=128][68]
    float* sP  = sKr;                   // [t=128][132], aliases Kr+Ki

    const int tid = threadIdx.x;
    const int ty = tid >> 4, tx = tid & 15;   // ty 0..31, tx 0..15
    const int t0 = blockIdx.x << 7;
    const int h = blockIdx.y, b = blockIdx.z;
    const size_t base = ((size_t)(b * HH + h)) * TT * HDIM;
    const int r0 = ty << 2;                   // 4 rows per thread
    const int c0 = tx << 2;                   // 4+4 cols per thread

    // load Q tile (transposed into [d][t])
#pragma unroll
    for (int i = 0; i < 4; i++) {
        int e = tid + i * 512;          // 0..2047
        int r = e >> 4, c4 = (e & 15) << 2;
        size_t g = base + (size_t)(t0 + r) * HDIM + c4;
        float4 qr = *(const float4*)&Qr[g];
        float4 qi = *(const float4*)&Qi[g];
        sQr[(c4 + 0) * 132 + r] = qr.x;
        sQr[(c4 + 1) * 132 + r] = qr.y;
        sQr[(c4 + 2) * 132 + r] = qr.z;
        sQr[(c4 + 3) * 132 + r] = qr.w;
        sQi[(c4 + 0) * 132 + r] = qi.x;
        sQi[(c4 + 1) * 132 + r] = qi.y;
        sQi[(c4 + 2) * 132 + r] = qi.z;
        sQi[(c4 + 3) * 132 + r] = qi.w;
    }

    float m[4], l[4];
    u64 acc2[4][2];                     // [row][col-pair]
#pragma unroll
    for (int i = 0; i < 4; i++) { m[i] = -INFINITY; l[i] = 0.f; }
#pragma unroll
    for (int i = 0; i < 4; i++) { acc2[i][0] = 0ull; acc2[i][1] = 0ull; }

    for (int s0 = 0; s0 < TT; s0 += 128) {
        __syncthreads();  // P/V consumed (and Q visible on first iter)
#pragma unroll
        for (int i = 0; i < 4; i++) {
            int e = tid + i * 512;
            int r = e >> 4, c4 = (e & 15) << 2;
            size_t g = base + (size_t)(s0 + r) * HDIM + c4;
            float4 kr = *(const float4*)&Kr[g];
            float4 ki = *(const float4*)&Ki[g];
            sKr[(c4 + 0) * 132 + r] = kr.x;
            sKr[(c4 + 1) * 132 + r] = kr.y;
            sKr[(c4 + 2) * 132 + r] = kr.z;
            sKr[(c4 + 3) * 132 + r] = kr.w;
            sKi[(c4 + 0) * 132 + r] = -ki.x;
            sKi[(c4 + 1) * 132 + r] = -ki.y;
            sKi[(c4 + 2) * 132 + r] = -ki.z;
            sKi[(c4 + 3) * 132 + r] = -ki.w;
            *(float4*)&sV[r * 68 + c4] = *(const float4*)&Vr[g];
        }
        __syncthreads();

        // ---- S tile: [4 rows][4 col-pairs]; K pairs direct from smem ----
        u64 S2[4][4];
#pragma unroll
        for (int i = 0; i < 4; i++)
#pragma unroll
            for (int j = 0; j < 4; j++) S2[i][j] = 0ull;

#pragma unroll 8
        for (int d = 0; d < 64; d++) {
            float4 q4 = *(const float4*)&sQr[d * 132 + r0];
            float4 p4 = *(const float4*)&sQi[d * 132 + r0];
            ulonglong2 K0 = *(const ulonglong2*)&sKr[d * 132 + c0];
            ulonglong2 K1 = *(const ulonglong2*)&sKr[d * 132 + 64 + c0];
            ulonglong2 J0 = *(const ulonglong2*)&sKi[d * 132 + c0];
            ulonglong2 J1 = *(const ulonglong2*)&sKi[d * 132 + 64 + c0];
            u64 kp[4] = {K0.x, K0.y, K1.x, K1.y};
            u64 jp[4] = {J0.x, J0.y, J1.x, J1.y};
            float qv[4] = {q4.x, q4.y, q4.z, q4.w};
            float pv_[4] = {p4.x, p4.y, p4.z, p4.w};
#pragma unroll
            for (int i = 0; i < 4; i++) {
                u64 qd = dup2(qv[i]);
                u64 pd = dup2(pv_[i]);
#pragma unroll
                for (int cp = 0; cp < 4; cp++) {
                    fma2(S2[i][cp], qd, kp[cp]);
                    fma2(S2[i][cp], pd, jp[cp]);
                }
            }
        }
        __syncthreads();  // all K reads done before P overwrites that smem

        float S[4][8];
#pragma unroll
        for (int i = 0; i < 4; i++)
#pragma unroll
            for (int cp = 0; cp < 4; cp++)
                upk2(S[i][2 * cp], S[i][2 * cp + 1], S2[i][cp]);

        // ---- online softmax; write P into aliased smem ----
        float corr[4];
#pragma unroll
        for (int i = 0; i < 4; i++) {
            float mx = S[i][0];
#pragma unroll
            for (int j = 1; j < 8; j++) mx = fmaxf(mx, S[i][j]);
            mx *= 0.125f;
#pragma unroll
            for (int o = 8; o >= 1; o >>= 1)
                mx = fmaxf(mx, __shfl_xor_sync(0xffffffffu, mx, o));
            float mn = fmaxf(m[i], mx);
            corr[i] = __expf(m[i] - mn);
            float ps = 0.f;
            float pv[8];
#pragma unroll
            for (int j = 0; j < 8; j++) {
                float p = __expf(S[i][j] * 0.125f - mn);
                pv[j] = p;
                ps += p;
            }
            *(float4*)&sP[(r0 + i) * 132 + c0] =
                make_float4(pv[0], pv[1], pv[2], pv[3]);
            *(float4*)&sP[(r0 + i) * 132 + 64 + c0] =
                make_float4(pv[4], pv[5], pv[6], pv[7]);
#pragma unroll
            for (int o = 8; o >= 1; o >>= 1)
                ps += __shfl_xor_sync(0xffffffffu, ps, o);
            l[i] = l[i] * corr[i] + ps;
            m[i] = mn;
        }
#pragma unroll
        for (int i = 0; i < 4; i++) {
            u64 cd = dup2(corr[i]);
            u64 t0r, t1r;
            mul2(t0r, acc2[i][0], cd);
            mul2(t1r, acc2[i][1], cd);
            acc2[i][0] = t0r;
            acc2[i][1] = t1r;
        }
        __syncthreads();

        // ---- O += P @ V: V pairs direct from smem, P scalars dup'd ----
#pragma unroll 8
        for (int s = 0; s < 128; s += 2) {
            ulonglong2 V0 = *(const ulonglong2*)&sV[s * 68 + c0];
            ulonglong2 V1 = *(const ulonglong2*)&sV[(s + 1) * 68 + c0];
#pragma unroll
            for (int i = 0; i < 4; i++) {
                float2 pp = *(const float2*)&sP[(r0 + i) * 132 + s];
                u64 pd0 = dup2(pp.x);
                u64 pd1 = dup2(pp.y);
                fma2(acc2[i][0], pd0, V0.x);
                fma2(acc2[i][1], pd0, V0.y);
                fma2(acc2[i][0], pd1, V1.x);
                fma2(acc2[i][1], pd1, V1.y);
            }
        }
    }

    // epilogue: normalize and write bf16x3 splits at [b, t, h*64+d]
#pragma unroll
    for (int i = 0; i < 4; i++) {
        float a[4];
        upk2(a[0], a[1], acc2[i][0]);
        upk2(a[2], a[3], acc2[i][1]);
        float inv = 1.f / l[i];
        size_t off = ((size_t)(b * TT + t0 + r0 + i)) * CC + h * HDIM + c0;
        __nv_bfloat162 h2[2], m2[2], l2[2];
#pragma unroll
        for (int c = 0; c < 4; c++) {
            float v = a[c] * inv;
            __nv_bfloat16 hb = __float2bfloat16(v);
            float r = v - __bfloat162float(hb);
            __nv_bfloat16 mb = __float2bfloat16(r);
            r -= __bfloat162float(mb);
            __nv_bfloat16 lb = __float2bfloat16(r);
            if (c & 1) {
                h2[c >> 1].y = hb; m2[c >> 1].y = mb; l2[c >> 1].y = lb;
            } else {
                h2[c >> 1].x = hb; m2[c >> 1].x = mb; l2[c >> 1].x = lb;
            }
        }
        *(__nv_bfloat162*)&Oh[off]     = h2[0];
        *(__nv_bfloat162*)&Oh[off + 2] = h2[1];
        *(__nv_bfloat162*)&Om[off]     = m2[0];
        *(__nv_bfloat162*)&Om[off + 2] = m2[1];
        *(__nv_bfloat162*)&Ol[off]     = l2[0];
        *(__nv_bfloat162*)&Ol[off + 2] = l2[1];
    }
}

// ----------------------------------------------------------------------------
// Final energy ratio: out = Y * (inE / (||Y row|| + 1e-8)) * energy_normalizer
// ----------------------------------------------------------------------------
__global__ void finalize_kernel(const float* __restrict__ Y,
                                const float* __restrict__ enorm,
                                float* __restrict__ out) {
    int row = blockIdx.x;
    const float* yr = Y + (size_t)row * CC;
    float s = 0.f;
    for (int c = threadIdx.x; c < CC; c += 256) {
        float v = yr[c];
        s += v * v;
    }
    float tot = blockReduceSum256(s);
    __shared__ float ratio;
    if (threadIdx.x == 0)
        ratio = g_inE[row] / (sqrtf(tot) + 1e-8f) * enorm[0];
    __syncthreads();
    for (int c = threadIdx.x; c < CC; c += 256)
        out[(size_t)row * CC + c] = yr[c] * ratio;
}

// ----------------------------------------------------------------------------
// Launch
// ----------------------------------------------------------------------------
extern "C" void kernel_launch(void* const* d_in, const int* in_sizes, int n_in,
                              void* d_out, int out_size) {
    const float* x      = (const float*)d_in[0];
    const float* fd     = (const float*)d_in[1];
    const float* wq     = (const float*)d_in[2];
    const float* bq     = (const float*)d_in[3];
    const float* wk     = (const float*)d_in[4];
    const float* bk     = (const float*)d_in[5];
    const float* wv     = (const float*)d_in[6];
    const float* bv     = (const float*)d_in[7];
    const float* wo     = (const float*)d_in[8];
    const float* bo     = (const float*)d_in[9];
    const float* alpha  = (const float*)d_in[10];
    const float* fas    = (const float*)d_in[11];
    const float* enorm  = (const float*)d_in[12];
    float* out = (float*)d_out;

    float *q, *k, *v, *qr, *qi, *kr, *ki, *vr, *y;
    __nv_bfloat16 *xh, *xm, *xl, *wt;
    cudaGetSymbolAddress((void**)&q,  g_q);
    cudaGetSymbolAddress((void**)&k,  g_k);
    cudaGetSymbolAddress((void**)&v,  g_v);
    cudaGetSymbolAddress((void**)&qr, g_qr);
    cudaGetSymbolAddress((void**)&qi, g_qi);
    cudaGetSymbolAddress((void**)&kr, g_kr);
    cudaGetSymbolAddress((void**)&ki, g_ki);
    cudaGetSymbolAddress((void**)&vr, g_vr);
    cudaGetSymbolAddress((void**)&y,  g_y);
    cudaGetSymbolAddress((void**)&xh, g_xh);
    cudaGetSymbolAddress((void**)&xm, g_xm);
    cudaGetSymbolAddress((void**)&xl, g_xl);
    cudaGetSymbolAddress((void**)&wt, g_wt);
    const size_t WSZ = (size_t)CC * CC;

    // fused: input energies + x split
    energy_split_kernel<<<BT, 256>>>(x, xh, xm, xl);

    // weight transpose+split
    dim3 wg(32, 32), wb(32, 8);
    wsplit_kernel<<<wg, wb>>>(wq, wt + 0 * WSZ, wt + 1 * WSZ, wt + 2 * WSZ);
    wsplit_kernel<<<wg, wb>>>(wk, wt + 3 * WSZ, wt + 4 * WSZ, wt + 5 * WSZ);
    wsplit_kernel<<<wg, wb>>>(wv, wt + 6 * WSZ, wt + 7 * WSZ, wt + 8 * WSZ);
    wsplit_kernel<<<wg, wb>>>(wo, wt + 9 * WSZ, wt + 10 * WSZ, wt + 11 * WSZ);

    // QKV projections on tensor cores (mma.sync bf16x3)
    static const int kTcSmem = 2 * 3 * 2 * 128 * ASTRIDE * (int)sizeof(__nv_bfloat16);
    cudaFuncSetAttribute(tc_gemm_kernel,
                         cudaFuncAttributeMaxDynamicSharedMemorySize, kTcSmem);
    dim3 gg(CC / 128, BT / 128);
    tc_gemm_kernel<<<gg, 256, kTcSmem>>>(xh, xm, xl,
                                         wt + 0 * WSZ, wt + 1 * WSZ, wt + 2 * WSZ,
                                         bq, q);
    tc_gemm_kernel<<<gg, 256, kTcSmem>>>(xh, xm, xl,
                                         wt + 3 * WSZ, wt + 4 * WSZ, wt + 5 * WSZ,
                                         bk, k);
    tc_gemm_kernel<<<gg, 256, kTcSmem>>>(xh, xm, xl,
                                         wt + 6 * WSZ, wt + 7 * WSZ, wt + 8 * WSZ,
                                         bv, v);

    // FFT + spectral filter, all three tensors in one launch
    static const int kFftSmem = TT * FSTR * (int)sizeof(float2);  // 147456
    cudaFuncSetAttribute(fft_filter_kernel,
                         cudaFuncAttributeMaxDynamicSharedMemorySize, kFftSmem);
    dim3 gf(HDIM / 8, HH * 3, BB);
    fft_filter_kernel<<<gf, 256, kFftSmem>>>(q, k, v, qr, qi, kr, ki, vr,
                                             fd, alpha, fas);

    // attention (writes O splits directly into xh/xm/xl)
    static const int kAttnSmem = (4 * 64 * 132 + 128 * 68) * (int)sizeof(float);
    cudaFuncSetAttribute(attn_kernel, cudaFuncAttributeMaxDynamicSharedMemorySize,
                         kAttnSmem);
    dim3 ga(TT / 128, HH, BB);
    attn_kernel<<<ga, 512, kAttnSmem>>>(qr, qi, kr, ki, vr, xh, xm, xl);

    // output projection
    tc_gemm_kernel<<<gg, 256, kTcSmem>>>(xh, xm, xl,
                                         wt + 9 * WSZ, wt + 10 * WSZ, wt + 11 * WSZ,
                                         bo, y);

    // energy-ratio epilogue
    finalize_kernel<<<BT, 256>>>(y, enorm, out);
}